// round 6
// baseline (speedup 1.0000x reference)
#include <cuda_runtime.h>
#include <math.h>
#include <stdint.h>

#define BATCH 16
#define SEQ   1024
#define DM    512
#define HD    64
#define DFF   2048
#define MTOT  (BATCH*SEQ)   // 16384
#define NLAYERS 4

// ---------------- scratch (static device globals; no allocation) -------------
__device__ float g_qkv[MTOT*192];                 // q|k|v packed per row
__device__ float g_E[(size_t)BATCH*SEQ*SEQ];      // exp(scores), 64 MB
__device__ float g_rs[MTOT];                      // 1/colsum per (b,key)
__device__ float g_v[MTOT*HD];                    // v * rs (tf32-rounded)
__device__ float g_head[MTOT*HD];
__device__ float g_t1[MTOT*DM];
__device__ float g_h[MTOT*DM];
__device__ float g_u[(size_t)MTOT*DFF];           // 128 MB
__device__ float g_t2[MTOT*DM];
__device__ float g_x[MTOT*DM];                    // trunk (tf32-rounded)
__device__ float g_x0[MTOT*DM];
__device__ float g_wqkv[DM*192];
__device__ float g_bqkv[192];
__device__ float g_weff[HD*DM];
__device__ float g_w1c[DM*DFF];
__device__ float g_w2c[DFF*DM];

__device__ __forceinline__ float tf32r(float x) {
    uint32_t u; asm("cvt.rna.tf32.f32 %0, %1;" : "=r"(u) : "f"(x));
    return __uint_as_float(u);
}
__device__ __forceinline__ void cpasync16(uint32_t s, const void* g) {
    asm volatile("cp.async.cg.shared.global [%0], [%1], 16;" :: "r"(s), "l"(g));
}

// ---------------- tf32 tensor-core GEMM, 4-stage single-sync pipeline --------
// C[M,ldc] = A[M,lda] @ B + bias (+resid), optional exp(x/8), optional tf32
// rounding of output. B normal: B[k,n] row-major. BTRANS: B is [n,k] row-major.
// Batched via blockIdx.z with element strides sA/sB/sC.
template<int BN, bool BTRANS, bool HASBIAS, bool RES, bool EXPSC, bool CVT>
__global__ __launch_bounds__(256, 2)
void mm_tc(const float* __restrict__ A, const float* __restrict__ Bm,
           const float* __restrict__ bias, const float* __restrict__ resid,
           float* __restrict__ C, int K, int lda, int ldb, int ldc,
           long long sA, long long sB, long long sC)
{
    constexpr int BM = 128, BK = 16, S = 4;
    constexpr int WN = BN / 2;       // warp n-extent (2 warp cols)
    constexpr int NF = WN / 8;       // n-fragments per warp
    constexpr int BSR = BTRANS ? BN : BK;
    constexpr int BSC = BTRANS ? (BK + 4) : (BN + 8);
    constexpr int ASZ = BM * (BK + 4);
    constexpr int BSZ = BSR * BSC;

    extern __shared__ float dyn[];
    float* Asb = dyn;                 // S stages of A
    float* Bsb = dyn + S * ASZ;       // S stages of B

    const int tid  = threadIdx.x;
    const int lane = tid & 31, warp = tid >> 5;
    const int wr = warp & 3, wc = warp >> 2;
    const int g = lane >> 2, q = lane & 3;
    const int m0 = blockIdx.y * BM;
    const int n0 = blockIdx.x * BN;
    const int z  = blockIdx.z;
    const float* Ab = A  + (size_t)z * sA;
    const float* Bb = Bm + (size_t)z * sB;

    auto stage = [&](int t, int s) {
        int k0 = t * BK;
        float* As = Asb + s * ASZ;
        float* Bs = Bsb + s * BSZ;
        #pragma unroll
        for (int p = 0; p < 2; p++) {                 // A: 128x16 = 512 f4
            int c = tid + p * 256;
            int r = c >> 2, kc = (c & 3) << 2;
            uint32_t sa = (uint32_t)__cvta_generic_to_shared(As + r * (BK + 4) + kc);
            cpasync16(sa, Ab + (size_t)(m0 + r) * lda + k0 + kc);
        }
        if (BTRANS) {
            #pragma unroll
            for (int p = 0; p < (BN * BK) / 1024; p++) {
                int c = tid + p * 256;
                int r = c >> 2, kc = (c & 3) << 2;
                uint32_t sa = (uint32_t)__cvta_generic_to_shared(Bs + r * BSC + kc);
                cpasync16(sa, Bb + (size_t)(n0 + r) * ldb + k0 + kc);
            }
        } else {
            constexpr int CPR = BN / 4;               // f4 chunks per B row
            #pragma unroll
            for (int p = 0; p < (BK * BN) / 1024; p++) {
                int c = tid + p * 256;
                int r = c / CPR, nc = (c % CPR) << 2;
                uint32_t sa = (uint32_t)__cvta_generic_to_shared(Bs + r * BSC + nc);
                cpasync16(sa, Bb + (size_t)(k0 + r) * ldb + n0 + nc);
            }
        }
        asm volatile("cp.async.commit_group;");
    };

    float acc[2][NF][4];
    #pragma unroll
    for (int i = 0; i < 2; i++)
        #pragma unroll
        for (int j = 0; j < NF; j++)
            #pragma unroll
            for (int c = 0; c < 4; c++) acc[i][j][c] = 0.f;

    const int mw = wr * 32;
    const int nw = wc * WN;
    const int T = K / BK;

    // preload S-1 stages
    #pragma unroll
    for (int i = 0; i < S - 1; i++)
        if (i < T) stage(i, i);

    for (int t = 0; t < T; t++) {
        const int rem = T - 1 - t;         // groups issued after group t
        if (rem >= 2)      asm volatile("cp.async.wait_group 2;");
        else if (rem == 1) asm volatile("cp.async.wait_group 1;");
        else               asm volatile("cp.async.wait_group 0;");
        __syncthreads();

        if (t + S - 1 < T) stage(t + S - 1, (t + S - 1) % S);

        const int s = t % S;
        const float* As = Asb + s * ASZ;
        const float* Bs = Bsb + s * BSZ;
        #pragma unroll
        for (int ks = 0; ks < BK; ks += 8) {
            uint32_t af[2][4];
            #pragma unroll
            for (int i = 0; i < 2; i++) {
                af[i][0] = __float_as_uint(As[(mw + i*16 + g    ) * (BK+4) + ks + q    ]);
                af[i][1] = __float_as_uint(As[(mw + i*16 + g + 8) * (BK+4) + ks + q    ]);
                af[i][2] = __float_as_uint(As[(mw + i*16 + g    ) * (BK+4) + ks + q + 4]);
                af[i][3] = __float_as_uint(As[(mw + i*16 + g + 8) * (BK+4) + ks + q + 4]);
            }
            uint32_t bf[NF][2];
            #pragma unroll
            for (int j = 0; j < NF; j++) {
                int n = nw + j * 8 + g;
                if (BTRANS) {
                    bf[j][0] = __float_as_uint(Bs[n * BSC + ks + q    ]);
                    bf[j][1] = __float_as_uint(Bs[n * BSC + ks + q + 4]);
                } else {
                    bf[j][0] = __float_as_uint(Bs[(ks + q    ) * BSC + n]);
                    bf[j][1] = __float_as_uint(Bs[(ks + q + 4) * BSC + n]);
                }
            }
            #pragma unroll
            for (int i = 0; i < 2; i++)
                #pragma unroll
                for (int j = 0; j < NF; j++)
                    asm volatile(
                        "mma.sync.aligned.m16n8k8.row.col.f32.tf32.tf32.f32 "
                        "{%0,%1,%2,%3}, {%4,%5,%6,%7}, {%8,%9}, {%0,%1,%2,%3};"
                        : "+f"(acc[i][j][0]), "+f"(acc[i][j][1]),
                          "+f"(acc[i][j][2]), "+f"(acc[i][j][3])
                        : "r"(af[i][0]), "r"(af[i][1]), "r"(af[i][2]), "r"(af[i][3]),
                          "r"(bf[j][0]), "r"(bf[j][1]));
        }
    }

    float* Cb = C + (size_t)z * sC;
    #pragma unroll
    for (int i = 0; i < 2; i++) {
        #pragma unroll
        for (int j = 0; j < NF; j++) {
            int col = n0 + nw + j * 8 + 2 * q;
            #pragma unroll
            for (int hh = 0; hh < 2; hh++) {
                int row = m0 + mw + i * 16 + g + hh * 8;
                float v0 = acc[i][j][hh * 2 + 0];
                float v1 = acc[i][j][hh * 2 + 1];
                if (EXPSC)  { v0 = __expf(v0 * 0.125f); v1 = __expf(v1 * 0.125f); }
                if (HASBIAS){ v0 += bias[col]; v1 += bias[col + 1]; }
                if (RES) {
                    v0 += resid[(size_t)row * ldc + col];
                    v1 += resid[(size_t)row * ldc + col + 1];
                }
                if (CVT) { v0 = tf32r(v0); v1 = tf32r(v1); }
                *(float2*)&Cb[(size_t)row * ldc + col] = make_float2(v0, v1);
            }
        }
    }
}

// ---------------- column sums of E: rs = 1/sum_i E[i,j] ----------------------
__global__ __launch_bounds__(256)
void colsum_k(const float* __restrict__ E, float* __restrict__ rs)
{
    __shared__ float sm[8][33];
    const int b = blockIdx.y, j0 = blockIdx.x * 32;
    const int jj = threadIdx.x & 31, ch = threadIdx.x >> 5;
    const float* Eb = E + (size_t)b * SEQ * SEQ;
    float s = 0.f;
    #pragma unroll 4
    for (int i = ch; i < SEQ; i += 8)
        s += Eb[(size_t)i * SEQ + j0 + jj];
    sm[ch][jj] = s;
    __syncthreads();
    if (ch == 0) {
        float t = 0.f;
        #pragma unroll
        for (int r = 0; r < 8; r++) t += sm[r][jj];
        rs[b * SEQ + j0 + jj] = 1.f / t;
    }
}

// ---------------- v' = v * rs (tf32-rounded) ---------------------------------
__global__ void scalev_k(const float* __restrict__ qkv, const float* __restrict__ rs,
                         float* __restrict__ vout)
{
    int idx = blockIdx.x * 256 + threadIdx.x;   // one float4 each
    int row = idx >> 4;
    int c4  = (idx & 15) << 2;
    float r = rs[row];
    float4 v = *(const float4*)&qkv[(size_t)row * 192 + 128 + c4];
    v.x = tf32r(v.x * r); v.y = tf32r(v.y * r);
    v.z = tf32r(v.z * r); v.w = tf32r(v.w * r);
    *(float4*)&vout[(size_t)row * 64 + c4] = v;
}

// ---------------- LayerNorm -------------------------------------------------
template<bool CVT>
__global__ __launch_bounds__(128)
void ln_kernel(const float* __restrict__ in, const float* __restrict__ gamma,
               const float* __restrict__ beta, float* __restrict__ out)
{
    __shared__ float red[8];
    const int row = blockIdx.x;
    const int tid = threadIdx.x;
    float4 v = ((const float4*)(in + (size_t)row * DM))[tid];
    float s  = v.x + v.y + v.z + v.w;
    float ss = v.x*v.x + v.y*v.y + v.z*v.z + v.w*v.w;
    #pragma unroll
    for (int o = 16; o > 0; o >>= 1) {
        s  += __shfl_xor_sync(0xffffffffu, s,  o);
        ss += __shfl_xor_sync(0xffffffffu, ss, o);
    }
    const int warp = tid >> 5;
    if ((tid & 31) == 0) { red[warp] = s; red[4 + warp] = ss; }
    __syncthreads();
    s  = red[0] + red[1] + red[2] + red[3];
    ss = red[4] + red[5] + red[6] + red[7];
    float mu  = s * (1.f / DM);
    float var = ss * (1.f / DM) - mu * mu;
    float inv = rsqrtf(var + 1e-5f);
    float4 g = ((const float4*)gamma)[tid];
    float4 b = ((const float4*)beta)[tid];
    float4 o;
    o.x = (v.x - mu) * inv * g.x + b.x;
    o.y = (v.y - mu) * inv * g.y + b.y;
    o.z = (v.z - mu) * inv * g.z + b.z;
    o.w = (v.w - mu) * inv * g.w + b.w;
    if (CVT) { o.x = tf32r(o.x); o.y = tf32r(o.y); o.z = tf32r(o.z); o.w = tf32r(o.w); }
    ((float4*)(out + (size_t)row * DM))[tid] = o;
}

// ---------------- prep kernels ----------------------------------------------
__global__ void prep_wqkv(const float* wq, const float* wk, const float* wv,
                          const float* bq, const float* bk, const float* bv,
                          float* w, float* bias)
{
    int idx = blockIdx.x * 256 + threadIdx.x;
    if (idx < DM * 192) {
        int r = idx / 192, c = idx % 192;
        float v = (c < 64) ? wq[r*64 + c] : (c < 128 ? wk[r*64 + c - 64] : wv[r*64 + c - 128]);
        w[idx] = tf32r(v);
    }
    if (idx < 192)
        bias[idx] = (idx < 64) ? bq[idx] : (idx < 128 ? bk[idx - 64] : bv[idx - 128]);
}

__global__ void prep_weff(const float* __restrict__ wo, float* __restrict__ weff)
{
    int idx = blockIdx.x * 256 + threadIdx.x;
    if (idx < HD * DM) {
        int r = idx / DM, c = idx % DM;
        float s = 0.f;
        #pragma unroll
        for (int h = 0; h < 8; h++) s += wo[(size_t)(h*HD + r) * DM + c];
        weff[idx] = tf32r(s);
    }
}

__global__ void cvt_copy(const float* __restrict__ in, float* __restrict__ out)
{
    int idx = blockIdx.x * 256 + threadIdx.x;   // one float4 each; grid sized exactly
    float4 v = ((const float4*)in)[idx];
    v.x = tf32r(v.x); v.y = tf32r(v.y); v.z = tf32r(v.z); v.w = tf32r(v.w);
    ((float4*)out)[idx] = v;
}

// ---------------- host orchestration ----------------------------------------
extern "C" void kernel_launch(void* const* d_in, const int* in_sizes, int n_in,
                              void* d_out, int out_size)
{
    (void)in_sizes; (void)n_in; (void)out_size;
    const float* x   = (const float*)d_in[0];
    const float* wq  = (const float*)d_in[1];
    const float* bq  = (const float*)d_in[2];
    const float* wk  = (const float*)d_in[3];
    const float* bk  = (const float*)d_in[4];
    const float* wv  = (const float*)d_in[5];
    const float* bv  = (const float*)d_in[6];
    const float* wo  = (const float*)d_in[7];
    const float* bo  = (const float*)d_in[8];
    const float* lng = (const float*)d_in[9];
    const float* lnb = (const float*)d_in[10];
    const float* w1  = (const float*)d_in[11];
    const float* b1  = (const float*)d_in[12];
    const float* w2  = (const float*)d_in[13];
    const float* b2  = (const float*)d_in[14];
    float* out = (float*)d_out;

    float *qkv, *E, *rs, *vv, *head, *t1, *h, *u, *t2, *xb, *x0;
    float *wqkvD, *bqkvD, *weffD, *w1c, *w2c;
    cudaGetSymbolAddress((void**)&qkv,  g_qkv);
    cudaGetSymbolAddress((void**)&E,    g_E);
    cudaGetSymbolAddress((void**)&rs,   g_rs);
    cudaGetSymbolAddress((void**)&vv,   g_v);
    cudaGetSymbolAddress((void**)&head, g_head);
    cudaGetSymbolAddress((void**)&t1,   g_t1);
    cudaGetSymbolAddress((void**)&h,    g_h);
    cudaGetSymbolAddress((void**)&u,    g_u);
    cudaGetSymbolAddress((void**)&t2,   g_t2);
    cudaGetSymbolAddress((void**)&xb,   g_x);
    cudaGetSymbolAddress((void**)&x0,   g_x0);
    cudaGetSymbolAddress((void**)&wqkvD, g_wqkv);
    cudaGetSymbolAddress((void**)&bqkvD, g_bqkv);
    cudaGetSymbolAddress((void**)&weffD, g_weff);
    cudaGetSymbolAddress((void**)&w1c,  g_w1c);
    cudaGetSymbolAddress((void**)&w2c,  g_w2c);

    // dynamic smem sizes (floats -> bytes): S=4 stages
    const int SM_QKV  = 4 * (128*20 + 16*72)  * 4;   // BN=64           59392
    const int SM_E    = 4 * (128*20 + 128*20) * 4;   // BN=128 BTRANS   81920
    const int SM_HEAD = SM_QKV;                      // BN=64
    const int SM_FF   = 4 * (128*20 + 16*136) * 4;   // BN=128          75776

    cudaFuncSetAttribute((const void*)mm_tc<64,  false, true,  false, false, true>,
                         cudaFuncAttributeMaxDynamicSharedMemorySize, SM_QKV);
    cudaFuncSetAttribute((const void*)mm_tc<128, true,  false, false, true,  true>,
                         cudaFuncAttributeMaxDynamicSharedMemorySize, SM_E);
    cudaFuncSetAttribute((const void*)mm_tc<64,  false, false, false, false, true>,
                         cudaFuncAttributeMaxDynamicSharedMemorySize, SM_HEAD);
    cudaFuncSetAttribute((const void*)mm_tc<128, false, true,  true,  false, false>,
                         cudaFuncAttributeMaxDynamicSharedMemorySize, SM_FF);
    cudaFuncSetAttribute((const void*)mm_tc<128, false, true,  false, false, true>,
                         cudaFuncAttributeMaxDynamicSharedMemorySize, SM_FF);

    // prep: pack/round weights, round input x
    prep_wqkv<<<(DM*192 + 255)/256, 256>>>(wq, wk, wv, bq, bk, bv, wqkvD, bqkvD);
    prep_weff<<<(HD*DM + 255)/256, 256>>>(wo, weffD);
    cvt_copy<<<(DM*DFF/4)/256, 256>>>(w1, w1c);
    cvt_copy<<<(DFF*DM/4)/256, 256>>>(w2, w2c);
    cvt_copy<<<((size_t)MTOT*DM/4)/256, 256>>>(x, x0);

    const float* xinA = x0;   // tf32-rounded trunk (GEMM A input)
    const float* xinR = x;    // residual (raw on layer 0)

    for (int L = 0; L < NLAYERS; L++) {
        // fused QKV: [16384,192] = x @ Wqkv + bqkv   (CVT out)
        mm_tc<64, false, true, false, false, true><<<dim3(3, 128, 1), 256, SM_QKV>>>(
            xinA, wqkvD, bqkvD, nullptr, qkv, DM, DM, 192, 192, 0, 0, 0);

        // E = exp(q @ k^T / 8) per batch  (CVT out)
        mm_tc<128, true, false, false, true, true><<<dim3(8, 8, 16), 256, SM_E>>>(
            qkv, qkv + 64, nullptr, nullptr, E, HD, 192, 192, SEQ,
            (long long)SEQ * 192, (long long)SEQ * 192, (long long)SEQ * SEQ);

        // column sums -> rs ; v' = v * rs
        colsum_k<<<dim3(SEQ/32, BATCH), 256>>>(E, rs);
        scalev_k<<<(MTOT * 16) / 256, 256>>>(qkv, rs, vv);

        // head = E @ v' per batch  (CVT out)
        mm_tc<64, false, false, false, false, true><<<dim3(1, 8, 16), 256, SM_HEAD>>>(
            E, vv, nullptr, nullptr, head, SEQ, SEQ, HD, HD,
            (long long)SEQ * SEQ, (long long)SEQ * HD, (long long)SEQ * HD);

        // t1 = head @ weff + bo + x ; h = LN(t1) (CVT)
        mm_tc<128, false, true, true, false, false><<<dim3(4, 128, 1), 256, SM_FF>>>(
            head, weffD, bo, xinR, t1, HD, HD, DM, DM, 0, 0, 0);
        ln_kernel<true><<<MTOT, 128>>>(t1, lng, lnb, h);

        // FF: u = h@w1+b1 (CVT) ; t2 = u@w2+b2+h ; x_next = LN(t2)
        mm_tc<128, false, true, false, false, true><<<dim3(16, 128, 1), 256, SM_FF>>>(
            h, w1c, b1, nullptr, u, DM, DM, DFF, DFF, 0, 0, 0);
        mm_tc<128, false, true, true, false, false><<<dim3(4, 128, 1), 256, SM_FF>>>(
            u, w2c, b2, h, t2, DFF, DFF, DM, DM, 0, 0, 0);
        if (L == NLAYERS - 1)
            ln_kernel<false><<<MTOT, 128>>>(t2, lng, lnb, out);
        else
            ln_kernel<true><<<MTOT, 128>>>(t2, lng, lnb, xb);

        xinA = xb;
        xinR = xb;
    }
}

// round 8
// speedup vs baseline: 1.6089x; 1.6089x over previous
#include <cuda_runtime.h>
#include <cuda_fp16.h>
#include <math.h>
#include <stdint.h>

#define BATCH 16
#define SEQ   1024
#define DM    512
#define HD    64
#define DFF   2048
#define MTOT  (BATCH*SEQ)   // 16384
#define NLAYERS 4

// ---------------- scratch (static device globals; no allocation) -------------
__device__ __half g_xh[MTOT*DM];                   // fp16 trunk (GEMM A)
__device__ __half g_qkvh[MTOT*192];                // q|k|v fp16
__device__ __half g_Eh[(size_t)BATCH*SEQ*SEQ];     // exp(scores) fp16, 32 MB
__device__ float  g_rs[MTOT];                      // 1/colsum per (b,key)
__device__ __half g_vt[BATCH*HD*SEQ];              // (v*rs*1024)^T per batch
__device__ __half g_headh[MTOT*HD];
__device__ float  g_t1[MTOT*DM];
__device__ float  g_h[MTOT*DM];                    // f32 (residual for FF2)
__device__ __half g_hh[MTOT*DM];                   // fp16 h (FF1 A)
__device__ __half g_uh[(size_t)MTOT*DFF];          // 64 MB
__device__ float  g_t2[MTOT*DM];
__device__ float  g_x[MTOT*DM];                    // f32 trunk (residual)
__device__ __half g_wqkvT[192*DM];                 // [192][512]
__device__ float  g_bqkv[192];
__device__ __half g_weffT[DM*HD];                  // [512][64]
__device__ __half g_w1t[DFF*DM];                   // [2048][512]
__device__ __half g_w2t[DM*DFF];                   // [512][2048]

__device__ __forceinline__ void cpasync16(uint32_t s, const void* g) {
    asm volatile("cp.async.cg.shared.global [%0], [%1], 16;" :: "r"(s), "l"(g));
}

// ---------------- fp16 tensor-core GEMM (m16n8k16), 2-stage pipeline ---------
// C[M,ldc] = A[M,lda] @ B^T + bias (+resid). A:[m][k] fp16, B:[n][k] fp16.
// Epilogue: v = acc*oscale; optional exp(v/8); +bias; +resid(f32);
// store fp16 (OUTH) or f32. Batched via blockIdx.z (element strides).
template<int BN, bool HASBIAS, bool RES, bool EXPSC, bool OUTH>
__global__ __launch_bounds__(256, 2)
void mm_h(const __half* __restrict__ A, const __half* __restrict__ B,
          const float* __restrict__ bias, const float* __restrict__ resid,
          __half* __restrict__ Ch, float* __restrict__ Cf,
          int K, int lda, int ldb, int ldc, float oscale,
          long long sA, long long sB, long long sC)
{
    constexpr int BM = 128, BK = 32, BKP = 40;
    constexpr int WN = BN / 2;       // warp n-extent (2 warp cols)
    constexpr int NF = WN / 8;       // n-fragments per warp
    __shared__ __align__(16) __half As[2][BM][BKP];
    __shared__ __align__(16) __half Bs[2][BN][BKP];

    const int tid  = threadIdx.x;
    const int lane = tid & 31, warp = tid >> 5;
    const int wr = warp & 3, wc = warp >> 2;
    const int g = lane >> 2, q = lane & 3;
    const int m0 = blockIdx.y * BM;
    const int n0 = blockIdx.x * BN;
    const int z  = blockIdx.z;
    const __half* Ab = A + (size_t)z * sA;
    const __half* Bb = B + (size_t)z * sB;

    auto stage = [&](int t, int s) {
        const int k0 = t * BK;
        #pragma unroll
        for (int p = 0; p < 2; p++) {                 // A: 128x32 halves = 512 x 16B
            int c = tid + p * 256;
            int r = c >> 2, kc = (c & 3) << 3;
            uint32_t sa = (uint32_t)__cvta_generic_to_shared(&As[s][r][kc]);
            cpasync16(sa, Ab + (size_t)(m0 + r) * lda + k0 + kc);
        }
        #pragma unroll
        for (int p = 0; p < BN / 64; p++) {           // B: BNx32 halves
            int c = tid + p * 256;
            int r = c >> 2, kc = (c & 3) << 3;
            uint32_t sa = (uint32_t)__cvta_generic_to_shared(&Bs[s][r][kc]);
            cpasync16(sa, Bb + (size_t)(n0 + r) * ldb + k0 + kc);
        }
        asm volatile("cp.async.commit_group;");
    };

    float acc[2][NF][4];
    #pragma unroll
    for (int i = 0; i < 2; i++)
        #pragma unroll
        for (int j = 0; j < NF; j++)
            #pragma unroll
            for (int c = 0; c < 4; c++) acc[i][j][c] = 0.f;

    const int mw = wr * 32;
    const int nw = wc * WN;
    const int T = K / BK;

    stage(0, 0);
    for (int t = 0; t < T; t++) {
        if (t + 1 < T) { stage(t + 1, (t + 1) & 1); asm volatile("cp.async.wait_group 1;"); }
        else           { asm volatile("cp.async.wait_group 0;"); }
        __syncthreads();
        const int s = t & 1;
        #pragma unroll
        for (int ks = 0; ks < BK; ks += 16) {
            uint32_t af[2][4];
            #pragma unroll
            for (int i = 0; i < 2; i++) {
                af[i][0] = *(const uint32_t*)&As[s][mw + i*16 + g    ][ks + 2*q    ];
                af[i][1] = *(const uint32_t*)&As[s][mw + i*16 + g + 8][ks + 2*q    ];
                af[i][2] = *(const uint32_t*)&As[s][mw + i*16 + g    ][ks + 2*q + 8];
                af[i][3] = *(const uint32_t*)&As[s][mw + i*16 + g + 8][ks + 2*q + 8];
            }
            uint32_t bf[NF][2];
            #pragma unroll
            for (int j = 0; j < NF; j++) {
                int n = nw + j * 8 + g;
                bf[j][0] = *(const uint32_t*)&Bs[s][n][ks + 2*q    ];
                bf[j][1] = *(const uint32_t*)&Bs[s][n][ks + 2*q + 8];
            }
            #pragma unroll
            for (int i = 0; i < 2; i++)
                #pragma unroll
                for (int j = 0; j < NF; j++)
                    asm volatile(
                        "mma.sync.aligned.m16n8k16.row.col.f32.f16.f16.f32 "
                        "{%0,%1,%2,%3}, {%4,%5,%6,%7}, {%8,%9}, {%0,%1,%2,%3};"
                        : "+f"(acc[i][j][0]), "+f"(acc[i][j][1]),
                          "+f"(acc[i][j][2]), "+f"(acc[i][j][3])
                        : "r"(af[i][0]), "r"(af[i][1]), "r"(af[i][2]), "r"(af[i][3]),
                          "r"(bf[j][0]), "r"(bf[j][1]));
        }
        __syncthreads();
    }

    #pragma unroll
    for (int i = 0; i < 2; i++) {
        #pragma unroll
        for (int j = 0; j < NF; j++) {
            int col = n0 + nw + j * 8 + 2 * q;
            #pragma unroll
            for (int hh = 0; hh < 2; hh++) {
                size_t row = (size_t)(m0 + mw + i * 16 + g + hh * 8);
                float v0 = acc[i][j][hh * 2 + 0] * oscale;
                float v1 = acc[i][j][hh * 2 + 1] * oscale;
                if (EXPSC)  { v0 = __expf(v0 * 0.125f); v1 = __expf(v1 * 0.125f); }
                if (HASBIAS){ v0 += bias[col]; v1 += bias[col + 1]; }
                if (RES) {
                    v0 += resid[row * ldc + col];
                    v1 += resid[row * ldc + col + 1];
                }
                if (OUTH) {
                    __half2 hv = __floats2half2_rn(v0, v1);
                    *(uint32_t*)&(Ch + (size_t)z * sC)[row * ldc + col] =
                        *(uint32_t*)&hv;
                } else {
                    *(float2*)&(Cf + (size_t)z * sC)[row * ldc + col] =
                        make_float2(v0, v1);
                }
            }
        }
    }
}

// ---------------- column sums of E: rs = 1/sum_i E[i,j] ----------------------
__global__ __launch_bounds__(256)
void colsum_k(const __half* __restrict__ E, float* __restrict__ rs)
{
    __shared__ float sm[8][33];
    const int b = blockIdx.y, j0 = blockIdx.x * 32;
    const int jj = threadIdx.x & 31, ch = threadIdx.x >> 5;
    const __half* Eb = E + (size_t)b * SEQ * SEQ;
    float s = 0.f;
    #pragma unroll 4
    for (int i = ch; i < SEQ; i += 8)
        s += __half2float(Eb[(size_t)i * SEQ + j0 + jj]);
    sm[ch][jj] = s;
    __syncthreads();
    if (ch == 0) {
        float t = 0.f;
        #pragma unroll
        for (int r = 0; r < 8; r++) t += sm[r][jj];
        rs[b * SEQ + j0 + jj] = 1.f / t;
    }
}

// ---------------- vt[b][d][key] = v[b,key,d] * rs * 1024 (smem transpose) ----
__global__ __launch_bounds__(256)
void scalevt_k(const __half* __restrict__ qkv, const float* __restrict__ rs,
               __half* __restrict__ vt)
{
    __shared__ __align__(16) __half sm[64][72];   // 144B row stride: uint4-safe
    __shared__ float rsm[64];
    const int b = blockIdx.y;
    const int key0 = blockIdx.x * 64;
    const int tid = threadIdx.x;
    // load tile: 64 keys x 64 dims (v part: cols 128..191 of qkv row)
    #pragma unroll
    for (int p = 0; p < 2; p++) {
        int c = tid + p * 256;                 // 512 chunks of 8 halves
        int kr = c >> 3, d8 = (c & 7) << 3;
        *(uint4*)&sm[kr][d8] =
            *(const uint4*)&qkv[((size_t)(b * SEQ + key0 + kr)) * 192 + 128 + d8];
    }
    if (tid < 64) rsm[tid] = rs[b * SEQ + key0 + tid] * 1024.f;
    __syncthreads();
    // write transposed: rows d (64), cols key (64)
    #pragma unroll
    for (int p = 0; p < 2; p++) {
        int c = tid + p * 256;
        int d = c >> 3, k8 = (c & 7) << 3;
        uint4 o;
        uint32_t* ow = (uint32_t*)&o;
        #pragma unroll
        for (int i = 0; i < 4; i++) {
            float f0 = __half2float(sm[k8 + 2*i    ][d]) * rsm[k8 + 2*i    ];
            float f1 = __half2float(sm[k8 + 2*i + 1][d]) * rsm[k8 + 2*i + 1];
            __half2 hv = __floats2half2_rn(f0, f1);
            ow[i] = *(uint32_t*)&hv;
        }
        *(uint4*)&vt[((size_t)(b * HD + d)) * SEQ + key0 + k8] = o;
    }
}

// ---------------- LayerNorm (f32 out; optional fp16 copy) --------------------
template<bool EMITH>
__global__ __launch_bounds__(128)
void ln_kernel(const float* __restrict__ in, const float* __restrict__ gamma,
               const float* __restrict__ beta, float* __restrict__ out,
               __half* __restrict__ outh)
{
    __shared__ float red[8];
    const int row = blockIdx.x;
    const int tid = threadIdx.x;
    float4 v = ((const float4*)(in + (size_t)row * DM))[tid];
    float s  = v.x + v.y + v.z + v.w;
    float ss = v.x*v.x + v.y*v.y + v.z*v.z + v.w*v.w;
    #pragma unroll
    for (int o = 16; o > 0; o >>= 1) {
        s  += __shfl_xor_sync(0xffffffffu, s,  o);
        ss += __shfl_xor_sync(0xffffffffu, ss, o);
    }
    const int warp = tid >> 5;
    if ((tid & 31) == 0) { red[warp] = s; red[4 + warp] = ss; }
    __syncthreads();
    s  = red[0] + red[1] + red[2] + red[3];
    ss = red[4] + red[5] + red[6] + red[7];
    float mu  = s * (1.f / DM);
    float var = ss * (1.f / DM) - mu * mu;
    float inv = rsqrtf(var + 1e-5f);
    float4 g = ((const float4*)gamma)[tid];
    float4 b = ((const float4*)beta)[tid];
    float4 o;
    o.x = (v.x - mu) * inv * g.x + b.x;
    o.y = (v.y - mu) * inv * g.y + b.y;
    o.z = (v.z - mu) * inv * g.z + b.z;
    o.w = (v.w - mu) * inv * g.w + b.w;
    ((float4*)(out + (size_t)row * DM))[tid] = o;
    if (EMITH) {
        __half2 h0 = __floats2half2_rn(o.x, o.y);
        __half2 h1 = __floats2half2_rn(o.z, o.w);
        *(uint2*)&outh[(size_t)row * DM + tid * 4] =
            make_uint2(*(uint32_t*)&h0, *(uint32_t*)&h1);
    }
}

// ---------------- prep kernels ----------------------------------------------
// wqkvT[c][r] (c in [0,192), r in [0,512))
__global__ void prep_wqkv(const float* wq, const float* wk, const float* wv,
                          const float* bq, const float* bk, const float* bv,
                          __half* wT, float* bias)
{
    int idx = blockIdx.x * 256 + threadIdx.x;
    if (idx < DM * 192) {
        int c = idx / DM, r = idx % DM;    // output row c, col r
        float v = (c < 64) ? wq[r*64 + c] : (c < 128 ? wk[r*64 + c - 64] : wv[r*64 + c - 128]);
        wT[idx] = __float2half_rn(v);
    }
    if (idx < 192)
        bias[idx] = (idx < 64) ? bq[idx] : (idx < 128 ? bk[idx - 64] : bv[idx - 128]);
}

// weffT[c][r] = sum_h wo[64h+r][c]   (c in [0,512), r in [0,64))
__global__ void prep_weff(const float* __restrict__ wo, __half* __restrict__ wT)
{
    int idx = blockIdx.x * 256 + threadIdx.x;
    if (idx < DM * HD) {
        int c = idx / HD, r = idx % HD;
        float s = 0.f;
        #pragma unroll
        for (int h = 0; h < 8; h++) s += wo[(size_t)(h*HD + r) * DM + c];
        wT[idx] = __float2half_rn(s);
    }
}

// W[R][C] -> T[C][R] fp16
__global__ void prep_t(const float* __restrict__ W, __half* __restrict__ T, int R, int C)
{
    int idx = blockIdx.x * 256 + threadIdx.x;
    if (idx < R * C) {
        int r = idx / C, c = idx % C;
        T[(size_t)c * R + r] = __float2half_rn(W[idx]);
    }
}

__global__ void cvt_h(const float* __restrict__ in, __half* __restrict__ out)
{
    int idx = blockIdx.x * 256 + threadIdx.x;   // one float4 -> half4 each
    float4 v = ((const float4*)in)[idx];
    __half2 h0 = __floats2half2_rn(v.x, v.y);
    __half2 h1 = __floats2half2_rn(v.z, v.w);
    ((uint2*)out)[idx] = make_uint2(*(uint32_t*)&h0, *(uint32_t*)&h1);
}

// ---------------- host orchestration ----------------------------------------
extern "C" void kernel_launch(void* const* d_in, const int* in_sizes, int n_in,
                              void* d_out, int out_size)
{
    (void)in_sizes; (void)n_in; (void)out_size;
    const float* x   = (const float*)d_in[0];
    const float* wq  = (const float*)d_in[1];
    const float* bq  = (const float*)d_in[2];
    const float* wk  = (const float*)d_in[3];
    const float* bk  = (const float*)d_in[4];
    const float* wv  = (const float*)d_in[5];
    const float* bv  = (const float*)d_in[6];
    const float* wo  = (const float*)d_in[7];
    const float* bo  = (const float*)d_in[8];
    const float* lng = (const float*)d_in[9];
    const float* lnb = (const float*)d_in[10];
    const float* w1  = (const float*)d_in[11];
    const float* b1  = (const float*)d_in[12];
    const float* w2  = (const float*)d_in[13];
    const float* b2  = (const float*)d_in[14];
    float* out = (float*)d_out;

    __half *xh, *qkvh, *Eh, *vt, *headh, *hh, *uh, *wqkvT, *weffT, *w1t, *w2t;
    float *rs, *t1, *h, *t2, *xb, *bqkvD;
    cudaGetSymbolAddress((void**)&xh,    g_xh);
    cudaGetSymbolAddress((void**)&qkvh,  g_qkvh);
    cudaGetSymbolAddress((void**)&Eh,    g_Eh);
    cudaGetSymbolAddress((void**)&rs,    g_rs);
    cudaGetSymbolAddress((void**)&vt,    g_vt);
    cudaGetSymbolAddress((void**)&headh, g_headh);
    cudaGetSymbolAddress((void**)&t1,    g_t1);
    cudaGetSymbolAddress((void**)&h,     g_h);
    cudaGetSymbolAddress((void**)&hh,    g_hh);
    cudaGetSymbolAddress((void**)&uh,    g_uh);
    cudaGetSymbolAddress((void**)&t2,    g_t2);
    cudaGetSymbolAddress((void**)&xb,    g_x);
    cudaGetSymbolAddress((void**)&wqkvT, g_wqkvT);
    cudaGetSymbolAddress((void**)&bqkvD, g_bqkv);
    cudaGetSymbolAddress((void**)&weffT, g_weffT);
    cudaGetSymbolAddress((void**)&w1t,   g_w1t);
    cudaGetSymbolAddress((void**)&w2t,   g_w2t);

    // prep: transpose/convert weights, fp16 input copy
    prep_wqkv<<<(DM*192 + 255)/256, 256>>>(wq, wk, wv, bq, bk, bv, wqkvT, bqkvD);
    prep_weff<<<(DM*HD + 255)/256, 256>>>(wo, weffT);
    prep_t<<<(DM*DFF + 255)/256, 256>>>(w1, w1t, DM, DFF);
    prep_t<<<(DFF*DM + 255)/256, 256>>>(w2, w2t, DFF, DM);
    cvt_h<<<((size_t)MTOT*DM/4)/256, 256>>>(x, xh);

    const __half* xinA = xh;  // fp16 trunk (GEMM A)
    const float*  xinR = x;   // f32 residual

    for (int L = 0; L < NLAYERS; L++) {
        // fused QKV: [16384,192] = x @ Wqkv + bqkv -> fp16
        mm_h<64, true, false, false, true><<<dim3(3, 128, 1), 256>>>(
            xinA, wqkvT, bqkvD, nullptr, qkvh, nullptr,
            DM, DM, DM, 192, 1.f, 0, 0, 0);

        // E = exp(q @ k^T / 8) per batch -> fp16
        mm_h<128, false, false, true, true><<<dim3(8, 8, 16), 256>>>(
            qkvh, qkvh + 64, nullptr, nullptr, Eh, nullptr,
            HD, 192, 192, SEQ, 1.f,
            (long long)SEQ * 192, (long long)SEQ * 192, (long long)SEQ * SEQ);

        // column sums -> rs ; vt = (v*rs*1024)^T
        colsum_k<<<dim3(SEQ/32, BATCH), 256>>>(Eh, rs);
        scalevt_k<<<dim3(SEQ/64, BATCH), 256>>>(qkvh, rs, vt);

        // head = (E @ vt^T) / 1024 per batch -> fp16
        mm_h<64, false, false, false, true><<<dim3(1, 8, 16), 256>>>(
            Eh, vt, nullptr, nullptr, headh, nullptr,
            SEQ, SEQ, SEQ, HD, 1.f / 1024.f,
            (long long)SEQ * SEQ, (long long)HD * SEQ, (long long)SEQ * HD);

        // t1 = head @ weff + bo + x ; h = LN(t1) (f32 + fp16)
        mm_h<128, true, true, false, false><<<dim3(4, 128, 1), 256>>>(
            headh, weffT, bo, xinR, nullptr, t1,
            HD, HD, HD, DM, 1.f, 0, 0, 0);
        ln_kernel<true><<<MTOT, 128>>>(t1, lng, lnb, h, hh);

        // FF1: u = h@w1+b1 -> fp16 ; FF2: t2 = u@w2+b2+h -> f32
        mm_h<128, true, false, false, true><<<dim3(16, 128, 1), 256>>>(
            hh, w1t, b1, nullptr, uh, nullptr,
            DM, DM, DM, DFF, 1.f, 0, 0, 0);
        mm_h<128, true, true, false, false><<<dim3(4, 128, 1), 256>>>(
            uh, w2t, b2, h, nullptr, t2,
            DFF, DFF, DFF, DM, 1.f, 0, 0, 0);

        if (L == NLAYERS - 1)
            ln_kernel<false><<<MTOT, 128>>>(t2, lng, lnb, out, nullptr);
        else
            ln_kernel<true><<<MTOT, 128>>>(t2, lng, lnb, xb, xh);

        xinA = xh;
        xinR = xb;
    }
}

// round 10
// speedup vs baseline: 3.2206x; 2.0018x over previous
#include <cuda_runtime.h>
#include <cuda_fp16.h>
#include <math.h>
#include <stdint.h>

#define BATCH 16
#define SEQ   1024
#define DM    512
#define HD    64
#define DFF   2048
#define MTOT  (BATCH*SEQ)   // 16384
#define NLAYERS 4

// ---------------- scratch (static device globals; no allocation) -------------
__device__ __half g_xh[MTOT*DM];                   // fp16 trunk (GEMM A)
__device__ __half g_qkvh[MTOT*192];                // q|k|v fp16
__device__ __half g_Eh[(size_t)BATCH*SEQ*SEQ];     // exp(scores) fp16, 32 MB
__device__ float  g_rs[MTOT];                      // 1/colsum per (b,key)
__device__ __half g_vt[BATCH*HD*SEQ];              // (v*rs*1024)^T per batch
__device__ __half g_headh[MTOT*HD];
__device__ float  g_t1[MTOT*DM];
__device__ float  g_h[MTOT*DM];                    // f32 (residual for FF)
__device__ __half g_hh[MTOT*DM];                   // fp16 h (FF A)
__device__ float  g_t2[MTOT*DM];
__device__ float  g_x[MTOT*DM];                    // f32 trunk (residual)
__device__ __half g_wqkvT[192*DM];                 // [192][512]
__device__ float  g_bqkv[192];
__device__ __half g_weffT[DM*HD];                  // [512][64]
__device__ __half g_w1h[DM*DFF];                   // w1 row-major fp16
__device__ __half g_w2t[DM*DFF];                   // w2^T [512][2048]
__device__ __half g_W12T[DM*DM];                   // (w1@w2)^T fp16 [n][k]
__device__ float  g_bff[DM];                       // b1@w2 + b2

__device__ __forceinline__ void cpasync16(uint32_t s, const void* g) {
    asm volatile("cp.async.cg.shared.global [%0], [%1], 16;" :: "r"(s), "l"(g));
}

// ---------------- fp16 tensor-core GEMM (m16n8k16), 2-stage pipeline ---------
// C[M,ldc] = A[M,lda] @ B^T + bias (+resid). A:[m][k] fp16, B:[n][k] fp16.
// Epilogue: v = acc*oscale; optional exp(v/8); +bias; +resid(f32);
// store fp16 (OUTH) or f32. Batched via blockIdx.z (element strides).
template<int BN, bool HASBIAS, bool RES, bool EXPSC, bool OUTH>
__global__ __launch_bounds__(256, 2)
void mm_h(const __half* __restrict__ A, const __half* __restrict__ B,
          const float* __restrict__ bias, const float* __restrict__ resid,
          __half* __restrict__ Ch, float* __restrict__ Cf,
          int K, int lda, int ldb, int ldc, float oscale,
          long long sA, long long sB, long long sC)
{
    constexpr int BM = 128, BK = 32, BKP = 40;
    constexpr int WN = BN / 2;       // warp n-extent (2 warp cols)
    constexpr int NF = WN / 8;       // n-fragments per warp
    __shared__ __align__(16) __half As[2][BM][BKP];
    __shared__ __align__(16) __half Bs[2][BN][BKP];

    const int tid  = threadIdx.x;
    const int lane = tid & 31, warp = tid >> 5;
    const int wr = warp & 3, wc = warp >> 2;
    const int g = lane >> 2, q = lane & 3;
    const int m0 = blockIdx.y * BM;
    const int n0 = blockIdx.x * BN;
    const int z  = blockIdx.z;
    const __half* Ab = A + (size_t)z * sA;
    const __half* Bb = B + (size_t)z * sB;

    auto stage = [&](int t, int s) {
        const int k0 = t * BK;
        #pragma unroll
        for (int p = 0; p < 2; p++) {                 // A: 128x32 halves = 512 x 16B
            int c = tid + p * 256;
            int r = c >> 2, kc = (c & 3) << 3;
            uint32_t sa = (uint32_t)__cvta_generic_to_shared(&As[s][r][kc]);
            cpasync16(sa, Ab + (size_t)(m0 + r) * lda + k0 + kc);
        }
        #pragma unroll
        for (int p = 0; p < BN / 64; p++) {           // B: BNx32 halves
            int c = tid + p * 256;
            int r = c >> 2, kc = (c & 3) << 3;
            uint32_t sa = (uint32_t)__cvta_generic_to_shared(&Bs[s][r][kc]);
            cpasync16(sa, Bb + (size_t)(n0 + r) * ldb + k0 + kc);
        }
        asm volatile("cp.async.commit_group;");
    };

    float acc[2][NF][4];
    #pragma unroll
    for (int i = 0; i < 2; i++)
        #pragma unroll
        for (int j = 0; j < NF; j++)
            #pragma unroll
            for (int c = 0; c < 4; c++) acc[i][j][c] = 0.f;

    const int mw = wr * 32;
    const int nw = wc * WN;
    const int T = K / BK;

    stage(0, 0);
    for (int t = 0; t < T; t++) {
        if (t + 1 < T) { stage(t + 1, (t + 1) & 1); asm volatile("cp.async.wait_group 1;"); }
        else           { asm volatile("cp.async.wait_group 0;"); }
        __syncthreads();
        const int s = t & 1;
        #pragma unroll
        for (int ks = 0; ks < BK; ks += 16) {
            uint32_t af[2][4];
            #pragma unroll
            for (int i = 0; i < 2; i++) {
                af[i][0] = *(const uint32_t*)&As[s][mw + i*16 + g    ][ks + 2*q    ];
                af[i][1] = *(const uint32_t*)&As[s][mw + i*16 + g + 8][ks + 2*q    ];
                af[i][2] = *(const uint32_t*)&As[s][mw + i*16 + g    ][ks + 2*q + 8];
                af[i][3] = *(const uint32_t*)&As[s][mw + i*16 + g + 8][ks + 2*q + 8];
            }
            uint32_t bf[NF][2];
            #pragma unroll
            for (int j = 0; j < NF; j++) {
                int n = nw + j * 8 + g;
                bf[j][0] = *(const uint32_t*)&Bs[s][n][ks + 2*q    ];
                bf[j][1] = *(const uint32_t*)&Bs[s][n][ks + 2*q + 8];
            }
            #pragma unroll
            for (int i = 0; i < 2; i++)
                #pragma unroll
                for (int j = 0; j < NF; j++)
                    asm volatile(
                        "mma.sync.aligned.m16n8k16.row.col.f32.f16.f16.f32 "
                        "{%0,%1,%2,%3}, {%4,%5,%6,%7}, {%8,%9}, {%0,%1,%2,%3};"
                        : "+f"(acc[i][j][0]), "+f"(acc[i][j][1]),
                          "+f"(acc[i][j][2]), "+f"(acc[i][j][3])
                        : "r"(af[i][0]), "r"(af[i][1]), "r"(af[i][2]), "r"(af[i][3]),
                          "r"(bf[j][0]), "r"(bf[j][1]));
        }
        __syncthreads();
    }

    #pragma unroll
    for (int i = 0; i < 2; i++) {
        #pragma unroll
        for (int j = 0; j < NF; j++) {
            int col = n0 + nw + j * 8 + 2 * q;
            #pragma unroll
            for (int hh = 0; hh < 2; hh++) {
                size_t row = (size_t)(m0 + mw + i * 16 + g + hh * 8);
                float v0 = acc[i][j][hh * 2 + 0] * oscale;
                float v1 = acc[i][j][hh * 2 + 1] * oscale;
                if (EXPSC)  { v0 = __expf(v0 * 0.125f); v1 = __expf(v1 * 0.125f); }
                if (HASBIAS){ v0 += bias[col]; v1 += bias[col + 1]; }
                if (RES) {
                    v0 += resid[row * ldc + col];
                    v1 += resid[row * ldc + col + 1];
                }
                if (OUTH) {
                    __half2 hv = __floats2half2_rn(v0, v1);
                    *(uint32_t*)&(Ch + (size_t)z * sC)[row * ldc + col] =
                        *(uint32_t*)&hv;
                } else {
                    *(float2*)&(Cf + (size_t)z * sC)[row * ldc + col] =
                        make_float2(v0, v1);
                }
            }
        }
    }
}

// ---------------- column sums of E: rs = 1/sum_i E[i,j] ----------------------
__global__ __launch_bounds__(256)
void colsum_k(const __half* __restrict__ E, float* __restrict__ rs)
{
    __shared__ float sm[8][33];
    const int b = blockIdx.y, j0 = blockIdx.x * 32;
    const int jj = threadIdx.x & 31, ch = threadIdx.x >> 5;
    const __half* Eb = E + (size_t)b * SEQ * SEQ;
    float s = 0.f;
    #pragma unroll 4
    for (int i = ch; i < SEQ; i += 8)
        s += __half2float(Eb[(size_t)i * SEQ + j0 + jj]);
    sm[ch][jj] = s;
    __syncthreads();
    if (ch == 0) {
        float t = 0.f;
        #pragma unroll
        for (int r = 0; r < 8; r++) t += sm[r][jj];
        rs[b * SEQ + j0 + jj] = 1.f / t;
    }
}

// ---------------- vt[b][d][key] = v[b,key,d] * rs * 1024 (smem transpose) ----
__global__ __launch_bounds__(256)
void scalevt_k(const __half* __restrict__ qkv, const float* __restrict__ rs,
               __half* __restrict__ vt)
{
    __shared__ __align__(16) __half sm[64][72];   // 144B row stride: uint4-safe
    __shared__ float rsm[64];
    const int b = blockIdx.y;
    const int key0 = blockIdx.x * 64;
    const int tid = threadIdx.x;
    #pragma unroll
    for (int p = 0; p < 2; p++) {
        int c = tid + p * 256;                 // 512 chunks of 8 halves
        int kr = c >> 3, d8 = (c & 7) << 3;
        *(uint4*)&sm[kr][d8] =
            *(const uint4*)&qkv[((size_t)(b * SEQ + key0 + kr)) * 192 + 128 + d8];
    }
    if (tid < 64) rsm[tid] = rs[b * SEQ + key0 + tid] * 1024.f;
    __syncthreads();
    #pragma unroll
    for (int p = 0; p < 2; p++) {
        int c = tid + p * 256;
        int d = c >> 3, k8 = (c & 7) << 3;
        uint4 o;
        uint32_t* ow = (uint32_t*)&o;
        #pragma unroll
        for (int i = 0; i < 4; i++) {
            float f0 = __half2float(sm[k8 + 2*i    ][d]) * rsm[k8 + 2*i    ];
            float f1 = __half2float(sm[k8 + 2*i + 1][d]) * rsm[k8 + 2*i + 1];
            __half2 hv = __floats2half2_rn(f0, f1);
            ow[i] = *(uint32_t*)&hv;
        }
        *(uint4*)&vt[((size_t)(b * HD + d)) * SEQ + key0 + k8] = o;
    }
}

// ---------------- LayerNorm (f32 out; optional fp16 copy) --------------------
template<bool EMITH>
__global__ __launch_bounds__(128)
void ln_kernel(const float* __restrict__ in, const float* __restrict__ gamma,
               const float* __restrict__ beta, float* __restrict__ out,
               __half* __restrict__ outh)
{
    __shared__ float red[8];
    const int row = blockIdx.x;
    const int tid = threadIdx.x;
    float4 v = ((const float4*)(in + (size_t)row * DM))[tid];
    float s  = v.x + v.y + v.z + v.w;
    float ss = v.x*v.x + v.y*v.y + v.z*v.z + v.w*v.w;
    #pragma unroll
    for (int o = 16; o > 0; o >>= 1) {
        s  += __shfl_xor_sync(0xffffffffu, s,  o);
        ss += __shfl_xor_sync(0xffffffffu, ss, o);
    }
    const int warp = tid >> 5;
    if ((tid & 31) == 0) { red[warp] = s; red[4 + warp] = ss; }
    __syncthreads();
    s  = red[0] + red[1] + red[2] + red[3];
    ss = red[4] + red[5] + red[6] + red[7];
    float mu  = s * (1.f / DM);
    float var = ss * (1.f / DM) - mu * mu;
    float inv = rsqrtf(var + 1e-5f);
    float4 g = ((const float4*)gamma)[tid];
    float4 b = ((const float4*)beta)[tid];
    float4 o;
    o.x = (v.x - mu) * inv * g.x + b.x;
    o.y = (v.y - mu) * inv * g.y + b.y;
    o.z = (v.z - mu) * inv * g.z + b.z;
    o.w = (v.w - mu) * inv * g.w + b.w;
    ((float4*)(out + (size_t)row * DM))[tid] = o;
    if (EMITH) {
        __half2 h0 = __floats2half2_rn(o.x, o.y);
        __half2 h1 = __floats2half2_rn(o.z, o.w);
        *(uint2*)&outh[(size_t)row * DM + tid * 4] =
            make_uint2(*(uint32_t*)&h0, *(uint32_t*)&h1);
    }
}

// ---------------- prep kernels ----------------------------------------------
__global__ void prep_wqkv(const float* wq, const float* wk, const float* wv,
                          const float* bq, const float* bk, const float* bv,
                          __half* wT, float* bias)
{
    int idx = blockIdx.x * 256 + threadIdx.x;
    if (idx < DM * 192) {
        int c = idx / DM, r = idx % DM;
        float v = (c < 64) ? wq[r*64 + c] : (c < 128 ? wk[r*64 + c - 64] : wv[r*64 + c - 128]);
        wT[idx] = __float2half_rn(v);
    }
    if (idx < 192)
        bias[idx] = (idx < 64) ? bq[idx] : (idx < 128 ? bk[idx - 64] : bv[idx - 128]);
}

__global__ void prep_weff(const float* __restrict__ wo, __half* __restrict__ wT)
{
    int idx = blockIdx.x * 256 + threadIdx.x;
    if (idx < DM * HD) {
        int c = idx / HD, r = idx % HD;
        float s = 0.f;
        #pragma unroll
        for (int h = 0; h < 8; h++) s += wo[(size_t)(h*HD + r) * DM + c];
        wT[idx] = __float2half_rn(s);
    }
}

// W[R][C] -> T[C][R] fp16
__global__ void prep_t(const float* __restrict__ W, __half* __restrict__ T, int R, int C)
{
    int idx = blockIdx.x * 256 + threadIdx.x;
    if (idx < R * C) {
        int r = idx / C, c = idx % C;
        T[(size_t)c * R + r] = __float2half_rn(W[idx]);
    }
}

__global__ void cvt_h(const float* __restrict__ in, __half* __restrict__ out)
{
    int idx = blockIdx.x * 256 + threadIdx.x;   // one float4 -> half4 each
    float4 v = ((const float4*)in)[idx];
    __half2 h0 = __floats2half2_rn(v.x, v.y);
    __half2 h1 = __floats2half2_rn(v.z, v.w);
    ((uint2*)out)[idx] = make_uint2(*(uint32_t*)&h0, *(uint32_t*)&h1);
}

// bff[n] = b2[n] + sum_k b1[k] * w2[k][n]   (fp32, coalesced over n)
__global__ __launch_bounds__(256)
void prep_bff(const float* __restrict__ b1, const float* __restrict__ w2,
              const float* __restrict__ b2, float* __restrict__ bff)
{
    int n = blockIdx.x * 256 + threadIdx.x;
    if (n < DM) {
        float s = b2[n];
        #pragma unroll 8
        for (int k = 0; k < DFF; k++)
            s += b1[k] * w2[(size_t)k * DM + n];
        bff[n] = s;
    }
}

// ---------------- host orchestration ----------------------------------------
extern "C" void kernel_launch(void* const* d_in, const int* in_sizes, int n_in,
                              void* d_out, int out_size)
{
    (void)in_sizes; (void)n_in; (void)out_size;
    const float* x   = (const float*)d_in[0];
    const float* wq  = (const float*)d_in[1];
    const float* bq  = (const float*)d_in[2];
    const float* wk  = (const float*)d_in[3];
    const float* bk  = (const float*)d_in[4];
    const float* wv  = (const float*)d_in[5];
    const float* bv  = (const float*)d_in[6];
    const float* wo  = (const float*)d_in[7];
    const float* bo  = (const float*)d_in[8];
    const float* lng = (const float*)d_in[9];
    const float* lnb = (const float*)d_in[10];
    const float* w1  = (const float*)d_in[11];
    const float* b1  = (const float*)d_in[12];
    const float* w2  = (const float*)d_in[13];
    const float* b2  = (const float*)d_in[14];
    float* out = (float*)d_out;

    __half *xh, *qkvh, *Eh, *vt, *headh, *hh, *wqkvT, *weffT, *w1h, *w2t, *W12T;
    float *rs, *t1, *h, *t2, *xb, *bqkvD, *bffD;
    cudaGetSymbolAddress((void**)&xh,    g_xh);
    cudaGetSymbolAddress((void**)&qkvh,  g_qkvh);
    cudaGetSymbolAddress((void**)&Eh,    g_Eh);
    cudaGetSymbolAddress((void**)&rs,    g_rs);
    cudaGetSymbolAddress((void**)&vt,    g_vt);
    cudaGetSymbolAddress((void**)&headh, g_headh);
    cudaGetSymbolAddress((void**)&t1,    g_t1);
    cudaGetSymbolAddress((void**)&h,     g_h);
    cudaGetSymbolAddress((void**)&hh,    g_hh);
    cudaGetSymbolAddress((void**)&t2,    g_t2);
    cudaGetSymbolAddress((void**)&xb,    g_x);
    cudaGetSymbolAddress((void**)&wqkvT, g_wqkvT);
    cudaGetSymbolAddress((void**)&bqkvD, g_bqkv);
    cudaGetSymbolAddress((void**)&weffT, g_weffT);
    cudaGetSymbolAddress((void**)&w1h,   g_w1h);
    cudaGetSymbolAddress((void**)&w2t,   g_w2t);
    cudaGetSymbolAddress((void**)&W12T,  g_W12T);
    cudaGetSymbolAddress((void**)&bffD,  g_bff);

    // prep: transpose/convert weights, fold FF weights, fp16 input copy
    prep_wqkv<<<(DM*192 + 255)/256, 256>>>(wq, wk, wv, bq, bk, bv, wqkvT, bqkvD);
    prep_weff<<<(DM*HD + 255)/256, 256>>>(wo, weffT);
    cvt_h<<<(DM*DFF/4)/256, 256>>>(w1, w1h);           // w1 row-major fp16
    prep_t<<<(DFF*DM + 255)/256, 256>>>(w2, w2t, DFF, DM);
    prep_bff<<<2, 256>>>(b1, w2, b2, bffD);
    cvt_h<<<((size_t)MTOT*DM/4)/256, 256>>>(x, xh);

    // W12T[n][m] = sum_k w2t[n][k] * w1h[m][k]  (=(w1@w2)^T, fp16)
    mm_h<64, false, false, false, true><<<dim3(DM/64, DM/128), 256>>>(
        w2t, w1h, nullptr, nullptr, W12T, nullptr,
        DFF, DFF, DFF, DM, 1.f, 0, 0, 0);

    const __half* xinA = xh;  // fp16 trunk (GEMM A)
    const float*  xinR = x;   // f32 residual

    for (int L = 0; L < NLAYERS; L++) {
        // fused QKV: [16384,192] = x @ Wqkv + bqkv -> fp16
        mm_h<64, true, false, false, true><<<dim3(3, 128, 1), 256>>>(
            xinA, wqkvT, bqkvD, nullptr, qkvh, nullptr,
            DM, DM, DM, 192, 1.f, 0, 0, 0);

        // E = exp(q @ k^T / 8) per batch -> fp16
        mm_h<128, false, false, true, true><<<dim3(8, 8, 16), 256>>>(
            qkvh, qkvh + 64, nullptr, nullptr, Eh, nullptr,
            HD, 192, 192, SEQ, 1.f,
            (long long)SEQ * 192, (long long)SEQ * 192, (long long)SEQ * SEQ);

        // column sums -> rs ; vt = (v*rs*1024)^T
        colsum_k<<<dim3(SEQ/32, BATCH), 256>>>(Eh, rs);
        scalevt_k<<<dim3(SEQ/64, BATCH), 256>>>(qkvh, rs, vt);

        // head = (E @ vt^T) / 1024 per batch -> fp16
        mm_h<64, false, false, false, true><<<dim3(1, 8, 16), 256>>>(
            Eh, vt, nullptr, nullptr, headh, nullptr,
            SEQ, SEQ, SEQ, HD, 1.f / 1024.f,
            (long long)SEQ * SEQ, (long long)HD * SEQ, (long long)SEQ * HD);

        // t1 = head @ weff + bo + x ; h = LN(t1) (f32 + fp16)
        mm_h<128, true, true, false, false><<<dim3(4, 128, 1), 256>>>(
            headh, weffT, bo, xinR, nullptr, t1,
            HD, HD, HD, DM, 1.f, 0, 0, 0);
        ln_kernel<true><<<MTOT, 128>>>(t1, lng, lnb, h, hh);

        // folded FF: t2 = h @ W12 + bff + h   (single GEMM, K=512)
        mm_h<128, true, true, false, false><<<dim3(4, 128, 1), 256>>>(
            hh, W12T, bffD, h, nullptr, t2,
            DM, DM, DM, DM, 1.f, 0, 0, 0);

        if (L == NLAYERS - 1)
            ln_kernel<false><<<MTOT, 128>>>(t2, lng, lnb, out, nullptr);
        else
            ln_kernel<true><<<MTOT, 128>>>(t2, lng, lnb, xb, xh);

        xinA = xh;
        xinR = xb;
    }
}

// round 11
// speedup vs baseline: 3.5139x; 1.0911x over previous
#include <cuda_runtime.h>
#include <cuda_fp16.h>
#include <math.h>
#include <stdint.h>

#define BATCH 16
#define SEQ   1024
#define DM    512
#define HD    64
#define DFF   2048
#define MTOT  (BATCH*SEQ)   // 16384
#define NLAYERS 4

// ---------------- scratch (static device globals; no allocation) -------------
__device__ __half g_xh[MTOT*DM];                   // fp16 trunk (GEMM A + resid)
__device__ __half g_qkvh[MTOT*192];                // q|k|v fp16
__device__ __half g_Eh[(size_t)BATCH*SEQ*SEQ];     // exp(scores) fp16, 32 MB
__device__ float  g_rs[MTOT];                      // colsum accumulators
__device__ __half g_vt[BATCH*HD*SEQ];              // (v*(1024/sum))^T per batch
__device__ __half g_headh[MTOT*HD];
__device__ float  g_t1[MTOT*DM];
__device__ __half g_hh[MTOT*DM];                   // fp16 h (FF A + resid)
__device__ float  g_t2[MTOT*DM];
__device__ __half g_wqkvT[192*DM];                 // [192][512]
__device__ float  g_bqkv[192];
__device__ __half g_weffT[DM*HD];                  // [512][64]
__device__ __half g_w1h[DM*DFF];                   // w1 row-major fp16
__device__ __half g_w2t[DM*DFF];                   // w2^T [512][2048]
__device__ __half g_W12T[DM*DM];                   // (w1@w2)^T fp16 [n][k]
__device__ float  g_bff[DM];                       // b1@w2 + b2

__device__ __forceinline__ void cpasync16(uint32_t s, const void* g) {
    asm volatile("cp.async.cg.shared.global [%0], [%1], 16;" :: "r"(s), "l"(g));
}

// ---------------- fp16 tensor-core GEMM (m16n8k16), 2-stage pipeline ---------
// C[M,ldc] = A[M,lda] @ B^T + bias (+fp16 resid). A:[m][k] fp16, B:[n][k] fp16.
// Epilogue: v = acc*oscale; optional exp(v/8); +bias; +resid(fp16);
// store fp16 (OUTH) or f32; optional per-column atomic sum (COLSUM).
template<int BN, bool HASBIAS, bool RES, bool EXPSC, bool OUTH, bool COLSUM>
__global__ __launch_bounds__(256, 2)
void mm_h(const __half* __restrict__ A, const __half* __restrict__ B,
          const float* __restrict__ bias, const __half* __restrict__ resid,
          __half* __restrict__ Ch, float* __restrict__ Cf,
          float* __restrict__ csout,
          int K, int lda, int ldb, int ldc, float oscale,
          long long sA, long long sB, long long sC)
{
    constexpr int BM = 128, BK = 32, BKP = 40;
    constexpr int WN = BN / 2;       // warp n-extent (2 warp cols)
    constexpr int NF = WN / 8;       // n-fragments per warp
    __shared__ __align__(16) __half As[2][BM][BKP];
    __shared__ __align__(16) __half Bs[2][BN][BKP];

    const int tid  = threadIdx.x;
    const int lane = tid & 31, warp = tid >> 5;
    const int wr = warp & 3, wc = warp >> 2;
    const int g = lane >> 2, q = lane & 3;
    const int m0 = blockIdx.y * BM;
    const int n0 = blockIdx.x * BN;
    const int z  = blockIdx.z;
    const __half* Ab = A + (size_t)z * sA;
    const __half* Bb = B + (size_t)z * sB;

    auto stage = [&](int t, int s) {
        const int k0 = t * BK;
        #pragma unroll
        for (int p = 0; p < 2; p++) {                 // A: 128x32 halves = 512 x 16B
            int c = tid + p * 256;
            int r = c >> 2, kc = (c & 3) << 3;
            uint32_t sa = (uint32_t)__cvta_generic_to_shared(&As[s][r][kc]);
            cpasync16(sa, Ab + (size_t)(m0 + r) * lda + k0 + kc);
        }
        #pragma unroll
        for (int p = 0; p < BN / 64; p++) {           // B: BNx32 halves
            int c = tid + p * 256;
            int r = c >> 2, kc = (c & 3) << 3;
            uint32_t sa = (uint32_t)__cvta_generic_to_shared(&Bs[s][r][kc]);
            cpasync16(sa, Bb + (size_t)(n0 + r) * ldb + k0 + kc);
        }
        asm volatile("cp.async.commit_group;");
    };

    float acc[2][NF][4];
    #pragma unroll
    for (int i = 0; i < 2; i++)
        #pragma unroll
        for (int j = 0; j < NF; j++)
            #pragma unroll
            for (int c = 0; c < 4; c++) acc[i][j][c] = 0.f;

    const int mw = wr * 32;
    const int nw = wc * WN;
    const int T = K / BK;

    stage(0, 0);
    for (int t = 0; t < T; t++) {
        if (t + 1 < T) { stage(t + 1, (t + 1) & 1); asm volatile("cp.async.wait_group 1;"); }
        else           { asm volatile("cp.async.wait_group 0;"); }
        __syncthreads();
        const int s = t & 1;
        #pragma unroll
        for (int ks = 0; ks < BK; ks += 16) {
            uint32_t af[2][4];
            #pragma unroll
            for (int i = 0; i < 2; i++) {
                af[i][0] = *(const uint32_t*)&As[s][mw + i*16 + g    ][ks + 2*q    ];
                af[i][1] = *(const uint32_t*)&As[s][mw + i*16 + g + 8][ks + 2*q    ];
                af[i][2] = *(const uint32_t*)&As[s][mw + i*16 + g    ][ks + 2*q + 8];
                af[i][3] = *(const uint32_t*)&As[s][mw + i*16 + g + 8][ks + 2*q + 8];
            }
            uint32_t bf[NF][2];
            #pragma unroll
            for (int j = 0; j < NF; j++) {
                int n = nw + j * 8 + g;
                bf[j][0] = *(const uint32_t*)&Bs[s][n][ks + 2*q    ];
                bf[j][1] = *(const uint32_t*)&Bs[s][n][ks + 2*q + 8];
            }
            #pragma unroll
            for (int i = 0; i < 2; i++)
                #pragma unroll
                for (int j = 0; j < NF; j++)
                    asm volatile(
                        "mma.sync.aligned.m16n8k16.row.col.f32.f16.f16.f32 "
                        "{%0,%1,%2,%3}, {%4,%5,%6,%7}, {%8,%9}, {%0,%1,%2,%3};"
                        : "+f"(acc[i][j][0]), "+f"(acc[i][j][1]),
                          "+f"(acc[i][j][2]), "+f"(acc[i][j][3])
                        : "r"(af[i][0]), "r"(af[i][1]), "r"(af[i][2]), "r"(af[i][3]),
                          "r"(bf[j][0]), "r"(bf[j][1]));
        }
        __syncthreads();
    }

    float cs[COLSUM ? NF : 1][2];
    if (COLSUM)
        #pragma unroll
        for (int j = 0; j < NF; j++) { cs[j][0] = 0.f; cs[j][1] = 0.f; }

    #pragma unroll
    for (int i = 0; i < 2; i++) {
        #pragma unroll
        for (int j = 0; j < NF; j++) {
            int col = n0 + nw + j * 8 + 2 * q;
            #pragma unroll
            for (int hh = 0; hh < 2; hh++) {
                size_t row = (size_t)(m0 + mw + i * 16 + g + hh * 8);
                float v0 = acc[i][j][hh * 2 + 0] * oscale;
                float v1 = acc[i][j][hh * 2 + 1] * oscale;
                if (EXPSC)  { v0 = __expf(v0 * 0.125f); v1 = __expf(v1 * 0.125f); }
                if (HASBIAS){ v0 += bias[col]; v1 += bias[col + 1]; }
                if (RES) {
                    __half2 rv = *(const __half2*)&resid[row * ldc + col];
                    float2 rf = __half22float2(rv);
                    v0 += rf.x; v1 += rf.y;
                }
                if (COLSUM) { cs[j][0] += v0; cs[j][1] += v1; }
                if (OUTH) {
                    __half2 hv = __floats2half2_rn(v0, v1);
                    *(uint32_t*)&(Ch + (size_t)z * sC)[row * ldc + col] =
                        *(uint32_t*)&hv;
                } else {
                    *(float2*)&(Cf + (size_t)z * sC)[row * ldc + col] =
                        make_float2(v0, v1);
                }
            }
        }
    }

    if (COLSUM) {
        #pragma unroll
        for (int j = 0; j < NF; j++) {
            #pragma unroll
            for (int c = 0; c < 2; c++) {
                float v = cs[j][c];
                v += __shfl_xor_sync(0xffffffffu, v, 4);
                v += __shfl_xor_sync(0xffffffffu, v, 8);
                v += __shfl_xor_sync(0xffffffffu, v, 16);
                if (g == 0)
                    atomicAdd(&csout[(size_t)z * SEQ + n0 + nw + j * 8 + 2 * q + c], v);
            }
        }
    }
}

// ---------------- zero colsum accumulators -----------------------------------
__global__ void zero_rs(float* __restrict__ rs)
{
    rs[blockIdx.x * 256 + threadIdx.x] = 0.f;
}

// ---------------- vt[b][d][key] = v[b,key,d] * 1024/sum (smem transpose) -----
__global__ __launch_bounds__(256)
void scalevt_k(const __half* __restrict__ qkv, const float* __restrict__ rs,
               __half* __restrict__ vt)
{
    __shared__ __align__(16) __half sm[64][72];   // 144B row stride: uint4-safe
    __shared__ float rsm[64];
    const int b = blockIdx.y;
    const int key0 = blockIdx.x * 64;
    const int tid = threadIdx.x;
    #pragma unroll
    for (int p = 0; p < 2; p++) {
        int c = tid + p * 256;                 // 512 chunks of 8 halves
        int kr = c >> 3, d8 = (c & 7) << 3;
        *(uint4*)&sm[kr][d8] =
            *(const uint4*)&qkv[((size_t)(b * SEQ + key0 + kr)) * 192 + 128 + d8];
    }
    if (tid < 64) rsm[tid] = 1024.f / rs[b * SEQ + key0 + tid];
    __syncthreads();
    #pragma unroll
    for (int p = 0; p < 2; p++) {
        int c = tid + p * 256;
        int d = c >> 3, k8 = (c & 7) << 3;
        uint4 o;
        uint32_t* ow = (uint32_t*)&o;
        #pragma unroll
        for (int i = 0; i < 4; i++) {
            float f0 = __half2float(sm[k8 + 2*i    ][d]) * rsm[k8 + 2*i    ];
            float f1 = __half2float(sm[k8 + 2*i + 1][d]) * rsm[k8 + 2*i + 1];
            __half2 hv = __floats2half2_rn(f0, f1);
            ow[i] = *(uint32_t*)&hv;
        }
        *(uint4*)&vt[((size_t)(b * HD + d)) * SEQ + key0 + k8] = o;
    }
}

// ---------------- LayerNorm: f32 in -> fp16 out OR f32 out -------------------
template<bool F32OUT>
__global__ __launch_bounds__(128)
void ln_kernel(const float* __restrict__ in, const float* __restrict__ gamma,
               const float* __restrict__ beta, float* __restrict__ outf,
               __half* __restrict__ outh)
{
    __shared__ float red[8];
    const int row = blockIdx.x;
    const int tid = threadIdx.x;
    float4 v = ((const float4*)(in + (size_t)row * DM))[tid];
    float s  = v.x + v.y + v.z + v.w;
    float ss = v.x*v.x + v.y*v.y + v.z*v.z + v.w*v.w;
    #pragma unroll
    for (int o = 16; o > 0; o >>= 1) {
        s  += __shfl_xor_sync(0xffffffffu, s,  o);
        ss += __shfl_xor_sync(0xffffffffu, ss, o);
    }
    const int warp = tid >> 5;
    if ((tid & 31) == 0) { red[warp] = s; red[4 + warp] = ss; }
    __syncthreads();
    s  = red[0] + red[1] + red[2] + red[3];
    ss = red[4] + red[5] + red[6] + red[7];
    float mu  = s * (1.f / DM);
    float var = ss * (1.f / DM) - mu * mu;
    float inv = rsqrtf(var + 1e-5f);
    float4 g = ((const float4*)gamma)[tid];
    float4 b = ((const float4*)beta)[tid];
    float4 o;
    o.x = (v.x - mu) * inv * g.x + b.x;
    o.y = (v.y - mu) * inv * g.y + b.y;
    o.z = (v.z - mu) * inv * g.z + b.z;
    o.w = (v.w - mu) * inv * g.w + b.w;
    if (F32OUT) {
        ((float4*)(outf + (size_t)row * DM))[tid] = o;
    } else {
        __half2 h0 = __floats2half2_rn(o.x, o.y);
        __half2 h1 = __floats2half2_rn(o.z, o.w);
        *(uint2*)&outh[(size_t)row * DM + tid * 4] =
            make_uint2(*(uint32_t*)&h0, *(uint32_t*)&h1);
    }
}

// ---------------- prep kernels ----------------------------------------------
__global__ void prep_wqkv(const float* wq, const float* wk, const float* wv,
                          const float* bq, const float* bk, const float* bv,
                          __half* wT, float* bias)
{
    int idx = blockIdx.x * 256 + threadIdx.x;
    if (idx < DM * 192) {
        int c = idx / DM, r = idx % DM;
        float v = (c < 64) ? wq[r*64 + c] : (c < 128 ? wk[r*64 + c - 64] : wv[r*64 + c - 128]);
        wT[idx] = __float2half_rn(v);
    }
    if (idx < 192)
        bias[idx] = (idx < 64) ? bq[idx] : (idx < 128 ? bk[idx - 64] : bv[idx - 128]);
}

__global__ void prep_weff(const float* __restrict__ wo, __half* __restrict__ wT)
{
    int idx = blockIdx.x * 256 + threadIdx.x;
    if (idx < DM * HD) {
        int c = idx / HD, r = idx % HD;
        float s = 0.f;
        #pragma unroll
        for (int h = 0; h < 8; h++) s += wo[(size_t)(h*HD + r) * DM + c];
        wT[idx] = __float2half_rn(s);
    }
}

// W[R][C] -> T[C][R] fp16
__global__ void prep_t(const float* __restrict__ W, __half* __restrict__ T, int R, int C)
{
    int idx = blockIdx.x * 256 + threadIdx.x;
    if (idx < R * C) {
        int r = idx / C, c = idx % C;
        T[(size_t)c * R + r] = __float2half_rn(W[idx]);
    }
}

__global__ void cvt_h(const float* __restrict__ in, __half* __restrict__ out)
{
    int idx = blockIdx.x * 256 + threadIdx.x;   // one float4 -> half4 each
    float4 v = ((const float4*)in)[idx];
    __half2 h0 = __floats2half2_rn(v.x, v.y);
    __half2 h1 = __floats2half2_rn(v.z, v.w);
    ((uint2*)out)[idx] = make_uint2(*(uint32_t*)&h0, *(uint32_t*)&h1);
}

// bff[n] = b2[n] + sum_k b1[k] * w2[k][n]
__global__ __launch_bounds__(256)
void prep_bff(const float* __restrict__ b1, const float* __restrict__ w2,
              const float* __restrict__ b2, float* __restrict__ bff)
{
    int n = blockIdx.x * 256 + threadIdx.x;
    if (n < DM) {
        float s = b2[n];
        #pragma unroll 8
        for (int k = 0; k < DFF; k++)
            s += b1[k] * w2[(size_t)k * DM + n];
        bff[n] = s;
    }
}

// ---------------- host orchestration ----------------------------------------
extern "C" void kernel_launch(void* const* d_in, const int* in_sizes, int n_in,
                              void* d_out, int out_size)
{
    (void)in_sizes; (void)n_in; (void)out_size;
    const float* x   = (const float*)d_in[0];
    const float* wq  = (const float*)d_in[1];
    const float* bq  = (const float*)d_in[2];
    const float* wk  = (const float*)d_in[3];
    const float* bk  = (const float*)d_in[4];
    const float* wv  = (const float*)d_in[5];
    const float* bv  = (const float*)d_in[6];
    const float* wo  = (const float*)d_in[7];
    const float* bo  = (const float*)d_in[8];
    const float* lng = (const float*)d_in[9];
    const float* lnb = (const float*)d_in[10];
    const float* w1  = (const float*)d_in[11];
    const float* b1  = (const float*)d_in[12];
    const float* w2  = (const float*)d_in[13];
    const float* b2  = (const float*)d_in[14];
    float* out = (float*)d_out;

    __half *xh, *qkvh, *Eh, *vt, *headh, *hh, *wqkvT, *weffT, *w1h, *w2t, *W12T;
    float *rs, *t1, *t2, *bqkvD, *bffD;
    cudaGetSymbolAddress((void**)&xh,    g_xh);
    cudaGetSymbolAddress((void**)&qkvh,  g_qkvh);
    cudaGetSymbolAddress((void**)&Eh,    g_Eh);
    cudaGetSymbolAddress((void**)&rs,    g_rs);
    cudaGetSymbolAddress((void**)&vt,    g_vt);
    cudaGetSymbolAddress((void**)&headh, g_headh);
    cudaGetSymbolAddress((void**)&t1,    g_t1);
    cudaGetSymbolAddress((void**)&hh,    g_hh);
    cudaGetSymbolAddress((void**)&t2,    g_t2);
    cudaGetSymbolAddress((void**)&wqkvT, g_wqkvT);
    cudaGetSymbolAddress((void**)&bqkvD, g_bqkv);
    cudaGetSymbolAddress((void**)&weffT, g_weffT);
    cudaGetSymbolAddress((void**)&w1h,   g_w1h);
    cudaGetSymbolAddress((void**)&w2t,   g_w2t);
    cudaGetSymbolAddress((void**)&W12T,  g_W12T);
    cudaGetSymbolAddress((void**)&bffD,  g_bff);

    // prep: transpose/convert weights, fold FF weights, fp16 input copy
    prep_wqkv<<<(DM*192 + 255)/256, 256>>>(wq, wk, wv, bq, bk, bv, wqkvT, bqkvD);
    prep_weff<<<(DM*HD + 255)/256, 256>>>(wo, weffT);
    cvt_h<<<(DM*DFF/4)/256, 256>>>(w1, w1h);
    prep_t<<<(DFF*DM + 255)/256, 256>>>(w2, w2t, DFF, DM);
    prep_bff<<<2, 256>>>(b1, w2, b2, bffD);
    cvt_h<<<((size_t)MTOT*DM/4)/256, 256>>>(x, xh);

    // W12T[n][m] = sum_k w2t[n][k] * w1h[m][k]  (=(w1@w2)^T, fp16)
    mm_h<64, false, false, false, true, false><<<dim3(DM/64, DM/128), 256>>>(
        w2t, w1h, nullptr, nullptr, W12T, nullptr, nullptr,
        DFF, DFF, DFF, DM, 1.f, 0, 0, 0);

    for (int L = 0; L < NLAYERS; L++) {
        // fused QKV: [16384,192] = x @ Wqkv + bqkv -> fp16
        mm_h<64, true, false, false, true, false><<<dim3(3, 128, 1), 256>>>(
            xh, wqkvT, bqkvD, nullptr, qkvh, nullptr, nullptr,
            DM, DM, DM, 192, 1.f, 0, 0, 0);

        // E = exp(q @ k^T / 8) per batch -> fp16, with fused column sums
        zero_rs<<<MTOT/256, 256>>>(rs);
        mm_h<128, false, false, true, true, true><<<dim3(8, 8, 16), 256>>>(
            qkvh, qkvh + 64, nullptr, nullptr, Eh, nullptr, rs,
            HD, 192, 192, SEQ, 1.f,
            (long long)SEQ * 192, (long long)SEQ * 192, (long long)SEQ * SEQ);

        // vt = (v * 1024/sum)^T
        scalevt_k<<<dim3(SEQ/64, BATCH), 256>>>(qkvh, rs, vt);

        // head = (E @ vt^T) / 1024 per batch -> fp16
        mm_h<64, false, false, false, true, false><<<dim3(1, 8, 16), 256>>>(
            Eh, vt, nullptr, nullptr, headh, nullptr, nullptr,
            SEQ, SEQ, SEQ, HD, 1.f / 1024.f,
            (long long)SEQ * SEQ, (long long)HD * SEQ, (long long)SEQ * HD);

        // t1 = head @ weff + bo + x(fp16) ; h = LN(t1) -> fp16
        mm_h<128, true, true, false, false, false><<<dim3(4, 128, 1), 256>>>(
            headh, weffT, bo, xh, nullptr, t1, nullptr,
            HD, HD, HD, DM, 1.f, 0, 0, 0);
        ln_kernel<false><<<MTOT, 128>>>(t1, lng, lnb, nullptr, hh);

        // folded FF: t2 = h @ W12 + bff + h(fp16)
        mm_h<128, true, true, false, false, false><<<dim3(4, 128, 1), 256>>>(
            hh, W12T, bffD, hh, nullptr, t2, nullptr,
            DM, DM, DM, DM, 1.f, 0, 0, 0);

        if (L == NLAYERS - 1)
            ln_kernel<true><<<MTOT, 128>>>(t2, lng, lnb, out, nullptr);
        else
            ln_kernel<false><<<MTOT, 128>>>(t2, lng, lnb, nullptr, xh);
    }
}

// round 12
// speedup vs baseline: 3.5619x; 1.0137x over previous
#include <cuda_runtime.h>
#include <cuda_fp16.h>
#include <math.h>
#include <stdint.h>

#define BATCH 16
#define SEQ   1024
#define DM    512
#define HD    64
#define DFF   2048
#define MTOT  (BATCH*SEQ)   // 16384
#define NLAYERS 4

// ---------------- scratch (static device globals; no allocation) -------------
__device__ __half g_xh[MTOT*DM];                   // fp16 trunk (GEMM A + resid)
__device__ __half g_qkvh[MTOT*192];                // q|k|v fp16
__device__ __half g_Eh[(size_t)BATCH*SEQ*SEQ];     // exp(scores) fp16, 32 MB
__device__ float  g_rs[MTOT];                      // colsum accumulators
__device__ __half g_vt[BATCH*HD*SEQ];              // (v*(1024/sum))^T per batch
__device__ __half g_headh[MTOT*HD];
__device__ float  g_t1[MTOT*DM];
__device__ __half g_hh[MTOT*DM];                   // fp16 h (FF A + resid)
__device__ float  g_t2[MTOT*DM];
__device__ __half g_wqkvT[192*DM];                 // [192][512]
__device__ float  g_bqkv[192];
__device__ __half g_weffT[DM*HD];                  // [512][64]
__device__ __half g_w1h[DM*DFF];                   // w1 row-major fp16
__device__ __half g_w2t[DM*DFF];                   // w2^T [512][2048]
__device__ __half g_W12T[DM*DM];                   // (w1@w2)^T fp16 [n][k]
__device__ float  g_bff[DM];                       // b1@w2 + b2

__device__ __forceinline__ void cpasync16(uint32_t s, const void* g) {
    asm volatile("cp.async.cg.shared.global [%0], [%1], 16;" :: "r"(s), "l"(g));
}

// ---------------- fp16 tensor-core GEMM (m16n8k16), 2-stage pipeline ---------
// C[M,ldc] = A[M,lda] @ B^T + bias (+fp16 resid). A:[m][k] fp16, B:[n][k] fp16.
// Epilogue: v = acc*oscale; EXPSC: store 2^v as fp16 via ex2.approx.f16x2
// (oscale carries /8*log2e); else +bias/+resid, store fp16 (OUTH) or f32.
// COLSUM: per-column sums of stored values accumulated into csout via atomics.
template<int BN, bool HASBIAS, bool RES, bool EXPSC, bool OUTH, bool COLSUM>
__global__ __launch_bounds__(256, 2)
void mm_h(const __half* __restrict__ A, const __half* __restrict__ B,
          const float* __restrict__ bias, const __half* __restrict__ resid,
          __half* __restrict__ Ch, float* __restrict__ Cf,
          float* __restrict__ csout,
          int K, int lda, int ldb, int ldc, float oscale,
          long long sA, long long sB, long long sC)
{
    constexpr int BM = 128, BK = 32, BKP = 40;
    constexpr int WN = BN / 2;       // warp n-extent (2 warp cols)
    constexpr int NF = WN / 8;       // n-fragments per warp
    __shared__ __align__(16) __half As[2][BM][BKP];
    __shared__ __align__(16) __half Bs[2][BN][BKP];

    const int tid  = threadIdx.x;
    const int lane = tid & 31, warp = tid >> 5;
    const int wr = warp & 3, wc = warp >> 2;
    const int g = lane >> 2, q = lane & 3;
    const int m0 = blockIdx.y * BM;
    const int n0 = blockIdx.x * BN;
    const int z  = blockIdx.z;
    const __half* Ab = A + (size_t)z * sA;
    const __half* Bb = B + (size_t)z * sB;

    auto stage = [&](int t, int s) {
        const int k0 = t * BK;
        #pragma unroll
        for (int p = 0; p < 2; p++) {                 // A: 128x32 halves = 512 x 16B
            int c = tid + p * 256;
            int r = c >> 2, kc = (c & 3) << 3;
            uint32_t sa = (uint32_t)__cvta_generic_to_shared(&As[s][r][kc]);
            cpasync16(sa, Ab + (size_t)(m0 + r) * lda + k0 + kc);
        }
        #pragma unroll
        for (int p = 0; p < BN / 64; p++) {           // B: BNx32 halves
            int c = tid + p * 256;
            int r = c >> 2, kc = (c & 3) << 3;
            uint32_t sa = (uint32_t)__cvta_generic_to_shared(&Bs[s][r][kc]);
            cpasync16(sa, Bb + (size_t)(n0 + r) * ldb + k0 + kc);
        }
        asm volatile("cp.async.commit_group;");
    };

    float acc[2][NF][4];
    #pragma unroll
    for (int i = 0; i < 2; i++)
        #pragma unroll
        for (int j = 0; j < NF; j++)
            #pragma unroll
            for (int c = 0; c < 4; c++) acc[i][j][c] = 0.f;

    const int mw = wr * 32;
    const int nw = wc * WN;
    const int T = K / BK;

    stage(0, 0);
    for (int t = 0; t < T; t++) {
        if (t + 1 < T) { stage(t + 1, (t + 1) & 1); asm volatile("cp.async.wait_group 1;"); }
        else           { asm volatile("cp.async.wait_group 0;"); }
        __syncthreads();
        const int s = t & 1;
        #pragma unroll
        for (int ks = 0; ks < BK; ks += 16) {
            uint32_t af[2][4];
            #pragma unroll
            for (int i = 0; i < 2; i++) {
                af[i][0] = *(const uint32_t*)&As[s][mw + i*16 + g    ][ks + 2*q    ];
                af[i][1] = *(const uint32_t*)&As[s][mw + i*16 + g + 8][ks + 2*q    ];
                af[i][2] = *(const uint32_t*)&As[s][mw + i*16 + g    ][ks + 2*q + 8];
                af[i][3] = *(const uint32_t*)&As[s][mw + i*16 + g + 8][ks + 2*q + 8];
            }
            uint32_t bf[NF][2];
            #pragma unroll
            for (int j = 0; j < NF; j++) {
                int n = nw + j * 8 + g;
                bf[j][0] = *(const uint32_t*)&Bs[s][n][ks + 2*q    ];
                bf[j][1] = *(const uint32_t*)&Bs[s][n][ks + 2*q + 8];
            }
            #pragma unroll
            for (int i = 0; i < 2; i++)
                #pragma unroll
                for (int j = 0; j < NF; j++)
                    asm volatile(
                        "mma.sync.aligned.m16n8k16.row.col.f32.f16.f16.f32 "
                        "{%0,%1,%2,%3}, {%4,%5,%6,%7}, {%8,%9}, {%0,%1,%2,%3};"
                        : "+f"(acc[i][j][0]), "+f"(acc[i][j][1]),
                          "+f"(acc[i][j][2]), "+f"(acc[i][j][3])
                        : "r"(af[i][0]), "r"(af[i][1]), "r"(af[i][2]), "r"(af[i][3]),
                          "r"(bf[j][0]), "r"(bf[j][1]));
        }
        __syncthreads();
    }

    float cs[COLSUM ? NF : 1][2];
    if (COLSUM)
        #pragma unroll
        for (int j = 0; j < NF; j++) { cs[j][0] = 0.f; cs[j][1] = 0.f; }

    #pragma unroll
    for (int i = 0; i < 2; i++) {
        #pragma unroll
        for (int j = 0; j < NF; j++) {
            int col = n0 + nw + j * 8 + 2 * q;
            #pragma unroll
            for (int hh = 0; hh < 2; hh++) {
                size_t row = (size_t)(m0 + mw + i * 16 + g + hh * 8);
                float v0 = acc[i][j][hh * 2 + 0] * oscale;
                float v1 = acc[i][j][hh * 2 + 1] * oscale;
                if (EXPSC) {
                    // E = 2^(s*log2e/8): one MUFU op per two elements
                    __half2 ah = __floats2half2_rn(v0, v1);
                    uint32_t eu;
                    asm("ex2.approx.f16x2 %0, %1;" : "=r"(eu) : "r"(*(uint32_t*)&ah));
                    *(uint32_t*)&(Ch + (size_t)z * sC)[row * ldc + col] = eu;
                    if (COLSUM) {
                        float2 ef = __half22float2(*(__half2*)&eu);
                        cs[j][0] += ef.x; cs[j][1] += ef.y;
                    }
                } else {
                    if (HASBIAS){ v0 += bias[col]; v1 += bias[col + 1]; }
                    if (RES) {
                        __half2 rv = *(const __half2*)&resid[row * ldc + col];
                        float2 rf = __half22float2(rv);
                        v0 += rf.x; v1 += rf.y;
                    }
                    if (OUTH) {
                        __half2 hv = __floats2half2_rn(v0, v1);
                        *(uint32_t*)&(Ch + (size_t)z * sC)[row * ldc + col] =
                            *(uint32_t*)&hv;
                    } else {
                        *(float2*)&(Cf + (size_t)z * sC)[row * ldc + col] =
                            make_float2(v0, v1);
                    }
                }
            }
        }
    }

    if (COLSUM) {
        #pragma unroll
        for (int j = 0; j < NF; j++) {
            #pragma unroll
            for (int c = 0; c < 2; c++) {
                float v = cs[j][c];
                v += __shfl_xor_sync(0xffffffffu, v, 4);
                v += __shfl_xor_sync(0xffffffffu, v, 8);
                v += __shfl_xor_sync(0xffffffffu, v, 16);
                if (g == 0)
                    atomicAdd(&csout[(size_t)z * SEQ + n0 + nw + j * 8 + 2 * q + c], v);
            }
        }
    }
}

// ---------------- zero colsum accumulators -----------------------------------
__global__ void zero_rs(float* __restrict__ rs)
{
    rs[blockIdx.x * 256 + threadIdx.x] = 0.f;
}

// ---------------- vt[b][d][key] = v[b,key,d] * 1024/sum (smem transpose) -----
__global__ __launch_bounds__(256)
void scalevt_k(const __half* __restrict__ qkv, const float* __restrict__ rs,
               __half* __restrict__ vt)
{
    __shared__ __align__(16) __half sm[64][72];   // 144B row stride: uint4-safe
    __shared__ float rsm[64];
    const int b = blockIdx.y;
    const int key0 = blockIdx.x * 64;
    const int tid = threadIdx.x;
    #pragma unroll
    for (int p = 0; p < 2; p++) {
        int c = tid + p * 256;                 // 512 chunks of 8 halves
        int kr = c >> 3, d8 = (c & 7) << 3;
        *(uint4*)&sm[kr][d8] =
            *(const uint4*)&qkv[((size_t)(b * SEQ + key0 + kr)) * 192 + 128 + d8];
    }
    if (tid < 64) rsm[tid] = 1024.f / rs[b * SEQ + key0 + tid];
    __syncthreads();
    #pragma unroll
    for (int p = 0; p < 2; p++) {
        int c = tid + p * 256;
        int d = c >> 3, k8 = (c & 7) << 3;
        uint4 o;
        uint32_t* ow = (uint32_t*)&o;
        #pragma unroll
        for (int i = 0; i < 4; i++) {
            float f0 = __half2float(sm[k8 + 2*i    ][d]) * rsm[k8 + 2*i    ];
            float f1 = __half2float(sm[k8 + 2*i + 1][d]) * rsm[k8 + 2*i + 1];
            __half2 hv = __floats2half2_rn(f0, f1);
            ow[i] = *(uint32_t*)&hv;
        }
        *(uint4*)&vt[((size_t)(b * HD + d)) * SEQ + key0 + k8] = o;
    }
}

// ---------------- LayerNorm: f32 in -> fp16 out OR f32 out -------------------
template<bool F32OUT>
__global__ __launch_bounds__(128)
void ln_kernel(const float* __restrict__ in, const float* __restrict__ gamma,
               const float* __restrict__ beta, float* __restrict__ outf,
               __half* __restrict__ outh)
{
    __shared__ float red[8];
    const int row = blockIdx.x;
    const int tid = threadIdx.x;
    float4 v = ((const float4*)(in + (size_t)row * DM))[tid];
    float s  = v.x + v.y + v.z + v.w;
    float ss = v.x*v.x + v.y*v.y + v.z*v.z + v.w*v.w;
    #pragma unroll
    for (int o = 16; o > 0; o >>= 1) {
        s  += __shfl_xor_sync(0xffffffffu, s,  o);
        ss += __shfl_xor_sync(0xffffffffu, ss, o);
    }
    const int warp = tid >> 5;
    if ((tid & 31) == 0) { red[warp] = s; red[4 + warp] = ss; }
    __syncthreads();
    s  = red[0] + red[1] + red[2] + red[3];
    ss = red[4] + red[5] + red[6] + red[7];
    float mu  = s * (1.f / DM);
    float var = ss * (1.f / DM) - mu * mu;
    float inv = rsqrtf(var + 1e-5f);
    float4 g = ((const float4*)gamma)[tid];
    float4 b = ((const float4*)beta)[tid];
    float4 o;
    o.x = (v.x - mu) * inv * g.x + b.x;
    o.y = (v.y - mu) * inv * g.y + b.y;
    o.z = (v.z - mu) * inv * g.z + b.z;
    o.w = (v.w - mu) * inv * g.w + b.w;
    if (F32OUT) {
        ((float4*)(outf + (size_t)row * DM))[tid] = o;
    } else {
        __half2 h0 = __floats2half2_rn(o.x, o.y);
        __half2 h1 = __floats2half2_rn(o.z, o.w);
        *(uint2*)&outh[(size_t)row * DM + tid * 4] =
            make_uint2(*(uint32_t*)&h0, *(uint32_t*)&h1);
    }
}

// ---------------- prep kernels ----------------------------------------------
__global__ void prep_wqkv(const float* wq, const float* wk, const float* wv,
                          const float* bq, const float* bk, const float* bv,
                          __half* wT, float* bias)
{
    int idx = blockIdx.x * 256 + threadIdx.x;
    if (idx < DM * 192) {
        int c = idx / DM, r = idx % DM;
        float v = (c < 64) ? wq[r*64 + c] : (c < 128 ? wk[r*64 + c - 64] : wv[r*64 + c - 128]);
        wT[idx] = __float2half_rn(v);
    }
    if (idx < 192)
        bias[idx] = (idx < 64) ? bq[idx] : (idx < 128 ? bk[idx - 64] : bv[idx - 128]);
}

__global__ void prep_weff(const float* __restrict__ wo, __half* __restrict__ wT)
{
    int idx = blockIdx.x * 256 + threadIdx.x;
    if (idx < DM * HD) {
        int c = idx / HD, r = idx % HD;
        float s = 0.f;
        #pragma unroll
        for (int h = 0; h < 8; h++) s += wo[(size_t)(h*HD + r) * DM + c];
        wT[idx] = __float2half_rn(s);
    }
}

// W[R][C] -> T[C][R] fp16
__global__ void prep_t(const float* __restrict__ W, __half* __restrict__ T, int R, int C)
{
    int idx = blockIdx.x * 256 + threadIdx.x;
    if (idx < R * C) {
        int r = idx / C, c = idx % C;
        T[(size_t)c * R + r] = __float2half_rn(W[idx]);
    }
}

__global__ void cvt_h(const float* __restrict__ in, __half* __restrict__ out)
{
    int idx = blockIdx.x * 256 + threadIdx.x;   // one float4 -> half4 each
    float4 v = ((const float4*)in)[idx];
    __half2 h0 = __floats2half2_rn(v.x, v.y);
    __half2 h1 = __floats2half2_rn(v.z, v.w);
    ((uint2*)out)[idx] = make_uint2(*(uint32_t*)&h0, *(uint32_t*)&h1);
}

// bff[n] = b2[n] + sum_k b1[k] * w2[k][n]
__global__ __launch_bounds__(256)
void prep_bff(const float* __restrict__ b1, const float* __restrict__ w2,
              const float* __restrict__ b2, float* __restrict__ bff)
{
    int n = blockIdx.x * 256 + threadIdx.x;
    if (n < DM) {
        float s = b2[n];
        #pragma unroll 8
        for (int k = 0; k < DFF; k++)
            s += b1[k] * w2[(size_t)k * DM + n];
        bff[n] = s;
    }
}

// ---------------- host orchestration ----------------------------------------
extern "C" void kernel_launch(void* const* d_in, const int* in_sizes, int n_in,
                              void* d_out, int out_size)
{
    (void)in_sizes; (void)n_in; (void)out_size;
    const float* x   = (const float*)d_in[0];
    const float* wq  = (const float*)d_in[1];
    const float* bq  = (const float*)d_in[2];
    const float* wk  = (const float*)d_in[3];
    const float* bk  = (const float*)d_in[4];
    const float* wv  = (const float*)d_in[5];
    const float* bv  = (const float*)d_in[6];
    const float* wo  = (const float*)d_in[7];
    const float* bo  = (const float*)d_in[8];
    const float* lng = (const float*)d_in[9];
    const float* lnb = (const float*)d_in[10];
    const float* w1  = (const float*)d_in[11];
    const float* b1  = (const float*)d_in[12];
    const float* w2  = (const float*)d_in[13];
    const float* b2  = (const float*)d_in[14];
    float* out = (float*)d_out;

    __half *xh, *qkvh, *Eh, *vt, *headh, *hh, *wqkvT, *weffT, *w1h, *w2t, *W12T;
    float *rs, *t1, *t2, *bqkvD, *bffD;
    cudaGetSymbolAddress((void**)&xh,    g_xh);
    cudaGetSymbolAddress((void**)&qkvh,  g_qkvh);
    cudaGetSymbolAddress((void**)&Eh,    g_Eh);
    cudaGetSymbolAddress((void**)&rs,    g_rs);
    cudaGetSymbolAddress((void**)&vt,    g_vt);
    cudaGetSymbolAddress((void**)&headh, g_headh);
    cudaGetSymbolAddress((void**)&t1,    g_t1);
    cudaGetSymbolAddress((void**)&hh,    g_hh);
    cudaGetSymbolAddress((void**)&t2,    g_t2);
    cudaGetSymbolAddress((void**)&wqkvT, g_wqkvT);
    cudaGetSymbolAddress((void**)&bqkvD, g_bqkv);
    cudaGetSymbolAddress((void**)&weffT, g_weffT);
    cudaGetSymbolAddress((void**)&w1h,   g_w1h);
    cudaGetSymbolAddress((void**)&w2t,   g_w2t);
    cudaGetSymbolAddress((void**)&W12T,  g_W12T);
    cudaGetSymbolAddress((void**)&bffD,  g_bff);

    // prep: transpose/convert weights, fold FF weights, fp16 input copy
    prep_wqkv<<<(DM*192 + 255)/256, 256>>>(wq, wk, wv, bq, bk, bv, wqkvT, bqkvD);
    prep_weff<<<(DM*HD + 255)/256, 256>>>(wo, weffT);
    cvt_h<<<(DM*DFF/4)/256, 256>>>(w1, w1h);
    prep_t<<<(DFF*DM + 255)/256, 256>>>(w2, w2t, DFF, DM);
    prep_bff<<<2, 256>>>(b1, w2, b2, bffD);
    cvt_h<<<((size_t)MTOT*DM/4)/256, 256>>>(x, xh);

    // W12T[n][m] = sum_k w2t[n][k] * w1h[m][k]  (=(w1@w2)^T, fp16)
    mm_h<64, false, false, false, true, false><<<dim3(DM/64, DM/128), 256>>>(
        w2t, w1h, nullptr, nullptr, W12T, nullptr, nullptr,
        DFF, DFF, DFF, DM, 1.f, 0, 0, 0);

    const float EXPSCALE = 0.125f * 1.4426950408889634f;  // /8 * log2(e)

    for (int L = 0; L < NLAYERS; L++) {
        // fused QKV: [16384,192] = x @ Wqkv + bqkv -> fp16
        mm_h<64, true, false, false, true, false><<<dim3(3, 128, 1), 256>>>(
            xh, wqkvT, bqkvD, nullptr, qkvh, nullptr, nullptr,
            DM, DM, DM, 192, 1.f, 0, 0, 0);

        // E = 2^(q@k^T * log2e/8) per batch -> fp16, with fused column sums
        zero_rs<<<MTOT/256, 256>>>(rs);
        mm_h<128, false, false, true, true, true><<<dim3(8, 8, 16), 256>>>(
            qkvh, qkvh + 64, nullptr, nullptr, Eh, nullptr, rs,
            HD, 192, 192, SEQ, EXPSCALE,
            (long long)SEQ * 192, (long long)SEQ * 192, (long long)SEQ * SEQ);

        // vt = (v * 1024/sum)^T
        scalevt_k<<<dim3(SEQ/64, BATCH), 256>>>(qkvh, rs, vt);

        // head = (E @ vt^T) / 1024 per batch -> fp16
        mm_h<64, false, false, false, true, false><<<dim3(1, 8, 16), 256>>>(
            Eh, vt, nullptr, nullptr, headh, nullptr, nullptr,
            SEQ, SEQ, SEQ, HD, 1.f / 1024.f,
            (long long)SEQ * SEQ, (long long)HD * SEQ, (long long)SEQ * HD);

        // t1 = head @ weff + bo + x(fp16) ; h = LN(t1) -> fp16
        mm_h<128, true, true, false, false, false><<<dim3(4, 128, 1), 256>>>(
            headh, weffT, bo, xh, nullptr, t1, nullptr,
            HD, HD, HD, DM, 1.f, 0, 0, 0);
        ln_kernel<false><<<MTOT, 128>>>(t1, lng, lnb, nullptr, hh);

        // folded FF: t2 = h @ W12 + bff + h(fp16)
        mm_h<128, true, true, false, false, false><<<dim3(4, 128, 1), 256>>>(
            hh, W12T, bffD, hh, nullptr, t2, nullptr,
            DM, DM, DM, DM, 1.f, 0, 0, 0);

        if (L == NLAYERS - 1)
            ln_kernel<true><<<MTOT, 128>>>(t2, lng, lnb, out, nullptr);
        else
            ln_kernel<false><<<MTOT, 128>>>(t2, lng, lnb, nullptr, xh);
    }
}

// round 13
// speedup vs baseline: 3.6917x; 1.0364x over previous
#include <cuda_runtime.h>
#include <cuda_fp16.h>
#include <math.h>
#include <stdint.h>

#define BATCH 16
#define SEQ   1024
#define DM    512
#define HD    64
#define DFF   2048
#define MTOT  (BATCH*SEQ)   // 16384
#define NLAYERS 4

// ---------------- scratch (static device globals; no allocation) -------------
__device__ __half g_xh[MTOT*DM];                   // fp16 trunk (GEMM A + resid)
__device__ __half g_qkvh[MTOT*192];                // q|k|v fp16
__device__ __half g_Eh[(size_t)BATCH*SEQ*SEQ];     // exp(scores) fp16, 32 MB
__device__ float  g_rs[MTOT];                      // colsum accumulators
__device__ __half g_vt[BATCH*HD*SEQ];              // (v*(1024/sum))^T per batch
__device__ __half g_headh[MTOT*HD];
__device__ float  g_t1[MTOT*DM];
__device__ __half g_hh[MTOT*DM];                   // fp16 h (FF A + resid)
__device__ float  g_t2[MTOT*DM];
__device__ __half g_wqkvT[192*DM];                 // [192][512]
__device__ float  g_bqkv[192];
__device__ __half g_weffT[DM*HD];                  // [512][64]
__device__ __half g_w1h[DM*DFF];                   // w1 row-major fp16
__device__ __half g_w2t[DM*DFF];                   // w2^T [512][2048]
__device__ __half g_W12T[DM*DM];                   // (w1@w2)^T fp16 [n][k]
__device__ float  g_bff[DM];                       // b1@w2 + b2

__device__ __forceinline__ void cpasync16(uint32_t s, const void* g) {
    asm volatile("cp.async.cg.shared.global [%0], [%1], 16;" :: "r"(s), "l"(g));
}

// ---------------- fp16 tensor-core GEMM (m16n8k16), 2-stage pipeline ---------
// C[M,ldc] = A[M,lda] @ B^T + bias (+fp16 resid). A:[m][k] fp16, B:[n][k] fp16.
// Epilogue: v = acc*oscale; EXPSC: store 2^v as fp16 via ex2.approx.f16x2
// (oscale carries /8*log2e); else +bias/+resid, store fp16 (OUTH) or f32.
// COLSUM: per-column sums of stored values accumulated into csout via atomics.
template<int BN, bool HASBIAS, bool RES, bool EXPSC, bool OUTH, bool COLSUM>
__global__ __launch_bounds__(256, 2)
void mm_h(const __half* __restrict__ A, const __half* __restrict__ B,
          const float* __restrict__ bias, const __half* __restrict__ resid,
          __half* __restrict__ Ch, float* __restrict__ Cf,
          float* __restrict__ csout,
          int K, int lda, int ldb, int ldc, float oscale,
          long long sA, long long sB, long long sC)
{
    constexpr int BM = 128, BK = 32, BKP = 40;
    constexpr int WN = BN / 2;       // warp n-extent (2 warp cols)
    constexpr int NF = WN / 8;       // n-fragments per warp
    __shared__ __align__(16) __half As[2][BM][BKP];
    __shared__ __align__(16) __half Bs[2][BN][BKP];

    const int tid  = threadIdx.x;
    const int lane = tid & 31, warp = tid >> 5;
    const int wr = warp & 3, wc = warp >> 2;
    const int g = lane >> 2, q = lane & 3;
    const int m0 = blockIdx.y * BM;
    const int n0 = blockIdx.x * BN;
    const int z  = blockIdx.z;
    const __half* Ab = A + (size_t)z * sA;
    const __half* Bb = B + (size_t)z * sB;

    auto stage = [&](int t, int s) {
        const int k0 = t * BK;
        #pragma unroll
        for (int p = 0; p < 2; p++) {                 // A: 128x32 halves = 512 x 16B
            int c = tid + p * 256;
            int r = c >> 2, kc = (c & 3) << 3;
            uint32_t sa = (uint32_t)__cvta_generic_to_shared(&As[s][r][kc]);
            cpasync16(sa, Ab + (size_t)(m0 + r) * lda + k0 + kc);
        }
        #pragma unroll
        for (int p = 0; p < BN / 64; p++) {           // B: BNx32 halves
            int c = tid + p * 256;
            int r = c >> 2, kc = (c & 3) << 3;
            uint32_t sa = (uint32_t)__cvta_generic_to_shared(&Bs[s][r][kc]);
            cpasync16(sa, Bb + (size_t)(n0 + r) * ldb + k0 + kc);
        }
        asm volatile("cp.async.commit_group;");
    };

    float acc[2][NF][4];
    #pragma unroll
    for (int i = 0; i < 2; i++)
        #pragma unroll
        for (int j = 0; j < NF; j++)
            #pragma unroll
            for (int c = 0; c < 4; c++) acc[i][j][c] = 0.f;

    const int mw = wr * 32;
    const int nw = wc * WN;
    const int T = K / BK;

    stage(0, 0);
    for (int t = 0; t < T; t++) {
        if (t + 1 < T) { stage(t + 1, (t + 1) & 1); asm volatile("cp.async.wait_group 1;"); }
        else           { asm volatile("cp.async.wait_group 0;"); }
        __syncthreads();
        const int s = t & 1;
        #pragma unroll
        for (int ks = 0; ks < BK; ks += 16) {
            uint32_t af[2][4];
            #pragma unroll
            for (int i = 0; i < 2; i++) {
                af[i][0] = *(const uint32_t*)&As[s][mw + i*16 + g    ][ks + 2*q    ];
                af[i][1] = *(const uint32_t*)&As[s][mw + i*16 + g + 8][ks + 2*q    ];
                af[i][2] = *(const uint32_t*)&As[s][mw + i*16 + g    ][ks + 2*q + 8];
                af[i][3] = *(const uint32_t*)&As[s][mw + i*16 + g + 8][ks + 2*q + 8];
            }
            uint32_t bf[NF][2];
            #pragma unroll
            for (int j = 0; j < NF; j++) {
                int n = nw + j * 8 + g;
                bf[j][0] = *(const uint32_t*)&Bs[s][n][ks + 2*q    ];
                bf[j][1] = *(const uint32_t*)&Bs[s][n][ks + 2*q + 8];
            }
            #pragma unroll
            for (int i = 0; i < 2; i++)
                #pragma unroll
                for (int j = 0; j < NF; j++)
                    asm volatile(
                        "mma.sync.aligned.m16n8k16.row.col.f32.f16.f16.f32 "
                        "{%0,%1,%2,%3}, {%4,%5,%6,%7}, {%8,%9}, {%0,%1,%2,%3};"
                        : "+f"(acc[i][j][0]), "+f"(acc[i][j][1]),
                          "+f"(acc[i][j][2]), "+f"(acc[i][j][3])
                        : "r"(af[i][0]), "r"(af[i][1]), "r"(af[i][2]), "r"(af[i][3]),
                          "r"(bf[j][0]), "r"(bf[j][1]));
        }
        __syncthreads();
    }

    float cs[COLSUM ? NF : 1][2];
    if (COLSUM)
        #pragma unroll
        for (int j = 0; j < NF; j++) { cs[j][0] = 0.f; cs[j][1] = 0.f; }

    #pragma unroll
    for (int i = 0; i < 2; i++) {
        #pragma unroll
        for (int j = 0; j < NF; j++) {
            int col = n0 + nw + j * 8 + 2 * q;
            #pragma unroll
            for (int hh = 0; hh < 2; hh++) {
                size_t row = (size_t)(m0 + mw + i * 16 + g + hh * 8);
                float v0 = acc[i][j][hh * 2 + 0] * oscale;
                float v1 = acc[i][j][hh * 2 + 1] * oscale;
                if (EXPSC) {
                    // E = 2^(s*log2e/8): one MUFU op per two elements
                    __half2 ah = __floats2half2_rn(v0, v1);
                    uint32_t eu;
                    asm("ex2.approx.f16x2 %0, %1;" : "=r"(eu) : "r"(*(uint32_t*)&ah));
                    *(uint32_t*)&(Ch + (size_t)z * sC)[row * ldc + col] = eu;
                    if (COLSUM) {
                        float2 ef = __half22float2(*(__half2*)&eu);
                        cs[j][0] += ef.x; cs[j][1] += ef.y;
                    }
                } else {
                    if (HASBIAS){ v0 += bias[col]; v1 += bias[col + 1]; }
                    if (RES) {
                        __half2 rv = *(const __half2*)&resid[row * ldc + col];
                        float2 rf = __half22float2(rv);
                        v0 += rf.x; v1 += rf.y;
                    }
                    if (OUTH) {
                        __half2 hv = __floats2half2_rn(v0, v1);
                        *(uint32_t*)&(Ch + (size_t)z * sC)[row * ldc + col] =
                            *(uint32_t*)&hv;
                    } else {
                        *(float2*)&(Cf + (size_t)z * sC)[row * ldc + col] =
                            make_float2(v0, v1);
                    }
                }
            }
        }
    }

    if (COLSUM) {
        #pragma unroll
        for (int j = 0; j < NF; j++) {
            #pragma unroll
            for (int c = 0; c < 2; c++) {
                float v = cs[j][c];
                v += __shfl_xor_sync(0xffffffffu, v, 4);
                v += __shfl_xor_sync(0xffffffffu, v, 8);
                v += __shfl_xor_sync(0xffffffffu, v, 16);
                if (g == 0)
                    atomicAdd(&csout[(size_t)z * SEQ + n0 + nw + j * 8 + 2 * q + c], v);
            }
        }
    }
}

// ---------------- zero colsum accumulators -----------------------------------
__global__ void zero_rs(float* __restrict__ rs)
{
    rs[blockIdx.x * 256 + threadIdx.x] = 0.f;
}

// ---------------- vt[b][d][key] = v[b,key,d] * 1024/sum (smem transpose) -----
__global__ __launch_bounds__(256)
void scalevt_k(const __half* __restrict__ qkv, const float* __restrict__ rs,
               __half* __restrict__ vt)
{
    __shared__ __align__(16) __half sm[64][72];   // 144B row stride: uint4-safe
    __shared__ float rsm[64];
    const int b = blockIdx.y;
    const int key0 = blockIdx.x * 64;
    const int tid = threadIdx.x;
    #pragma unroll
    for (int p = 0; p < 2; p++) {
        int c = tid + p * 256;                 // 512 chunks of 8 halves
        int kr = c >> 3, d8 = (c & 7) << 3;
        *(uint4*)&sm[kr][d8] =
            *(const uint4*)&qkv[((size_t)(b * SEQ + key0 + kr)) * 192 + 128 + d8];
    }
    if (tid < 64) rsm[tid] = 1024.f / rs[b * SEQ + key0 + tid];
    __syncthreads();
    #pragma unroll
    for (int p = 0; p < 2; p++) {
        int c = tid + p * 256;
        int d = c >> 3, k8 = (c & 7) << 3;
        uint4 o;
        uint32_t* ow = (uint32_t*)&o;
        #pragma unroll
        for (int i = 0; i < 4; i++) {
            float f0 = __half2float(sm[k8 + 2*i    ][d]) * rsm[k8 + 2*i    ];
            float f1 = __half2float(sm[k8 + 2*i + 1][d]) * rsm[k8 + 2*i + 1];
            __half2 hv = __floats2half2_rn(f0, f1);
            ow[i] = *(uint32_t*)&hv;
        }
        *(uint4*)&vt[((size_t)(b * HD + d)) * SEQ + key0 + k8] = o;
    }
}

// ---------------- LayerNorm: warp-per-row, 8 rows/block ----------------------
// f32 in -> fp16 out (F32OUT=false) or f32 out (F32OUT=true)
template<bool F32OUT>
__global__ __launch_bounds__(256)
void ln_kernel(const float* __restrict__ in, const float* __restrict__ gamma,
               const float* __restrict__ beta, float* __restrict__ outf,
               __half* __restrict__ outh)
{
    const int warp = threadIdx.x >> 5, lane = threadIdx.x & 31;
    const size_t row = (size_t)blockIdx.x * 8 + warp;
    const float4* ip = (const float4*)(in + row * DM);

    float4 v[4];
    float s = 0.f, ss = 0.f;
    #pragma unroll
    for (int i = 0; i < 4; i++) {
        v[i] = ip[lane + 32 * i];
        s  += v[i].x + v[i].y + v[i].z + v[i].w;
        ss += v[i].x*v[i].x + v[i].y*v[i].y + v[i].z*v[i].z + v[i].w*v[i].w;
    }
    #pragma unroll
    for (int o = 16; o > 0; o >>= 1) {
        s  += __shfl_xor_sync(0xffffffffu, s,  o);
        ss += __shfl_xor_sync(0xffffffffu, ss, o);
    }
    const float mu  = s * (1.f / DM);
    const float var = ss * (1.f / DM) - mu * mu;
    const float inv = rsqrtf(var + 1e-5f);

    #pragma unroll
    for (int i = 0; i < 4; i++) {
        float4 g = ((const float4*)gamma)[lane + 32 * i];
        float4 b = ((const float4*)beta)[lane + 32 * i];
        float4 o;
        o.x = (v[i].x - mu) * inv * g.x + b.x;
        o.y = (v[i].y - mu) * inv * g.y + b.y;
        o.z = (v[i].z - mu) * inv * g.z + b.z;
        o.w = (v[i].w - mu) * inv * g.w + b.w;
        if (F32OUT) {
            ((float4*)(outf + row * DM))[lane + 32 * i] = o;
        } else {
            __half2 h0 = __floats2half2_rn(o.x, o.y);
            __half2 h1 = __floats2half2_rn(o.z, o.w);
            *(uint2*)&outh[row * DM + (lane + 32 * i) * 4] =
                make_uint2(*(uint32_t*)&h0, *(uint32_t*)&h1);
        }
    }
}

// ---------------- prep kernels ----------------------------------------------
__global__ void prep_wqkv(const float* wq, const float* wk, const float* wv,
                          const float* bq, const float* bk, const float* bv,
                          __half* wT, float* bias)
{
    int idx = blockIdx.x * 256 + threadIdx.x;
    if (idx < DM * 192) {
        int c = idx / DM, r = idx % DM;
        float v = (c < 64) ? wq[r*64 + c] : (c < 128 ? wk[r*64 + c - 64] : wv[r*64 + c - 128]);
        wT[idx] = __float2half_rn(v);
    }
    if (idx < 192)
        bias[idx] = (idx < 64) ? bq[idx] : (idx < 128 ? bk[idx - 64] : bv[idx - 128]);
}

__global__ void prep_weff(const float* __restrict__ wo, __half* __restrict__ wT)
{
    int idx = blockIdx.x * 256 + threadIdx.x;
    if (idx < DM * HD) {
        int c = idx / HD, r = idx % HD;
        float s = 0.f;
        #pragma unroll
        for (int h = 0; h < 8; h++) s += wo[(size_t)(h*HD + r) * DM + c];
        wT[idx] = __float2half_rn(s);
    }
}

// W[R][C] -> T[C][R] fp16
__global__ void prep_t(const float* __restrict__ W, __half* __restrict__ T, int R, int C)
{
    int idx = blockIdx.x * 256 + threadIdx.x;
    if (idx < R * C) {
        int r = idx / C, c = idx % C;
        T[(size_t)c * R + r] = __float2half_rn(W[idx]);
    }
}

__global__ void cvt_h(const float* __restrict__ in, __half* __restrict__ out)
{
    int idx = blockIdx.x * 256 + threadIdx.x;   // one float4 -> half4 each
    float4 v = ((const float4*)in)[idx];
    __half2 h0 = __floats2half2_rn(v.x, v.y);
    __half2 h1 = __floats2half2_rn(v.z, v.w);
    ((uint2*)out)[idx] = make_uint2(*(uint32_t*)&h0, *(uint32_t*)&h1);
}

// bff[n] = b2[n] + sum_k b1[k] * w2[k][n]
__global__ __launch_bounds__(256)
void prep_bff(const float* __restrict__ b1, const float* __restrict__ w2,
              const float* __restrict__ b2, float* __restrict__ bff)
{
    int n = blockIdx.x * 256 + threadIdx.x;
    if (n < DM) {
        float s = b2[n];
        #pragma unroll 8
        for (int k = 0; k < DFF; k++)
            s += b1[k] * w2[(size_t)k * DM + n];
        bff[n] = s;
    }
}

// ---------------- host orchestration ----------------------------------------
extern "C" void kernel_launch(void* const* d_in, const int* in_sizes, int n_in,
                              void* d_out, int out_size)
{
    (void)in_sizes; (void)n_in; (void)out_size;
    const float* x   = (const float*)d_in[0];
    const float* wq  = (const float*)d_in[1];
    const float* bq  = (const float*)d_in[2];
    const float* wk  = (const float*)d_in[3];
    const float* bk  = (const float*)d_in[4];
    const float* wv  = (const float*)d_in[5];
    const float* bv  = (const float*)d_in[6];
    const float* wo  = (const float*)d_in[7];
    const float* bo  = (const float*)d_in[8];
    const float* lng = (const float*)d_in[9];
    const float* lnb = (const float*)d_in[10];
    const float* w1  = (const float*)d_in[11];
    const float* b1  = (const float*)d_in[12];
    const float* w2  = (const float*)d_in[13];
    const float* b2  = (const float*)d_in[14];
    float* out = (float*)d_out;

    __half *xh, *qkvh, *Eh, *vt, *headh, *hh, *wqkvT, *weffT, *w1h, *w2t, *W12T;
    float *rs, *t1, *t2, *bqkvD, *bffD;
    cudaGetSymbolAddress((void**)&xh,    g_xh);
    cudaGetSymbolAddress((void**)&qkvh,  g_qkvh);
    cudaGetSymbolAddress((void**)&Eh,    g_Eh);
    cudaGetSymbolAddress((void**)&rs,    g_rs);
    cudaGetSymbolAddress((void**)&vt,    g_vt);
    cudaGetSymbolAddress((void**)&headh, g_headh);
    cudaGetSymbolAddress((void**)&t1,    g_t1);
    cudaGetSymbolAddress((void**)&hh,    g_hh);
    cudaGetSymbolAddress((void**)&t2,    g_t2);
    cudaGetSymbolAddress((void**)&wqkvT, g_wqkvT);
    cudaGetSymbolAddress((void**)&bqkvD, g_bqkv);
    cudaGetSymbolAddress((void**)&weffT, g_weffT);
    cudaGetSymbolAddress((void**)&w1h,   g_w1h);
    cudaGetSymbolAddress((void**)&w2t,   g_w2t);
    cudaGetSymbolAddress((void**)&W12T,  g_W12T);
    cudaGetSymbolAddress((void**)&bffD,  g_bff);

    // prep: transpose/convert weights, fold FF weights, fp16 input copy
    prep_wqkv<<<(DM*192 + 255)/256, 256>>>(wq, wk, wv, bq, bk, bv, wqkvT, bqkvD);
    prep_weff<<<(DM*HD + 255)/256, 256>>>(wo, weffT);
    cvt_h<<<(DM*DFF/4)/256, 256>>>(w1, w1h);
    prep_t<<<(DFF*DM + 255)/256, 256>>>(w2, w2t, DFF, DM);
    prep_bff<<<2, 256>>>(b1, w2, b2, bffD);
    cvt_h<<<((size_t)MTOT*DM/4)/256, 256>>>(x, xh);

    // W12T[n][m] = sum_k w2t[n][k] * w1h[m][k]  (=(w1@w2)^T, fp16)
    mm_h<64, false, false, false, true, false><<<dim3(DM/64, DM/128), 256>>>(
        w2t, w1h, nullptr, nullptr, W12T, nullptr, nullptr,
        DFF, DFF, DFF, DM, 1.f, 0, 0, 0);

    const float EXPSCALE = 0.125f * 1.4426950408889634f;  // /8 * log2(e)

    for (int L = 0; L < NLAYERS; L++) {
        // fused QKV: [16384,192] = x @ Wqkv + bqkv -> fp16
        mm_h<64, true, false, false, true, false><<<dim3(3, 128, 1), 256>>>(
            xh, wqkvT, bqkvD, nullptr, qkvh, nullptr, nullptr,
            DM, DM, DM, 192, 1.f, 0, 0, 0);

        // E = 2^(q@k^T * log2e/8) per batch -> fp16, with fused column sums
        zero_rs<<<MTOT/256, 256>>>(rs);
        mm_h<128, false, false, true, true, true><<<dim3(8, 8, 16), 256>>>(
            qkvh, qkvh + 64, nullptr, nullptr, Eh, nullptr, rs,
            HD, 192, 192, SEQ, EXPSCALE,
            (long long)SEQ * 192, (long long)SEQ * 192, (long long)SEQ * SEQ);

        // vt = (v * 1024/sum)^T
        scalevt_k<<<dim3(SEQ/64, BATCH), 256>>>(qkvh, rs, vt);

        // head = (E @ vt^T) / 1024 per batch -> fp16
        mm_h<64, false, false, false, true, false><<<dim3(1, 8, 16), 256>>>(
            Eh, vt, nullptr, nullptr, headh, nullptr, nullptr,
            SEQ, SEQ, SEQ, HD, 1.f / 1024.f,
            (long long)SEQ * SEQ, (long long)HD * SEQ, (long long)SEQ * HD);

        // t1 = head @ weff + bo + x(fp16) ; h = LN(t1) -> fp16
        mm_h<128, true, true, false, false, false><<<dim3(4, 128, 1), 256>>>(
            headh, weffT, bo, xh, nullptr, t1, nullptr,
            HD, HD, HD, DM, 1.f, 0, 0, 0);
        ln_kernel<false><<<MTOT/8, 256>>>(t1, lng, lnb, nullptr, hh);

        // folded FF: t2 = h @ W12 + bff + h(fp16)
        mm_h<128, true, true, false, false, false><<<dim3(4, 128, 1), 256>>>(
            hh, W12T, bffD, hh, nullptr, t2, nullptr,
            DM, DM, DM, DM, 1.f, 0, 0, 0);

        if (L == NLAYERS - 1)
            ln_kernel<true><<<MTOT/8, 256>>>(t2, lng, lnb, out, nullptr);
        else
            ln_kernel<false><<<MTOT/8, 256>>>(t2, lng, lnb, nullptr, xh);
    }
}

// round 14
// speedup vs baseline: 4.2771x; 1.1586x over previous
#include <cuda_runtime.h>
#include <cuda_fp16.h>
#include <math.h>
#include <stdint.h>

#define BATCH 16
#define SEQ   1024
#define DM    512
#define HD    64
#define DFF   2048
#define MTOT  (BATCH*SEQ)   // 16384
#define NLAYERS 4

// ---------------- scratch (static device globals; no allocation) -------------
__device__ __half g_xh[MTOT*DM];                   // fp16 trunk (GEMM A + resid)
__device__ __half g_qkvh[MTOT*192];                // q|k|v fp16
__device__ __half g_Eh[(size_t)BATCH*SEQ*SEQ];     // exp(scores) fp16, 32 MB
__device__ float  g_rs[MTOT];                      // colsum accumulators
__device__ __half g_vt[BATCH*HD*SEQ];              // (v*(1024/sum))^T per batch
__device__ __half g_headh[MTOT*HD];
__device__ float  g_t1[MTOT*DM];
__device__ __half g_hh[MTOT*DM];                   // fp16 h (FF A + resid)
__device__ float  g_t2[MTOT*DM];
__device__ __half g_wqkvT[192*DM];                 // [192][512]
__device__ float  g_bqkv[192];
__device__ __half g_weffT[DM*HD];                  // [512][64]
__device__ __half g_w1h[DM*DFF];                   // w1 row-major fp16
__device__ __half g_w2t[DM*DFF];                   // w2^T [512][2048]
__device__ __half g_W12T[DM*DM];                   // (w1@w2)^T fp16 [n][k]
__device__ float  g_bff[DM];                       // b1@w2 + b2

__device__ __forceinline__ void cpasync16(uint32_t s, const void* g) {
    asm volatile("cp.async.cg.shared.global [%0], [%1], 16;" :: "r"(s), "l"(g));
}

// ---------------- fp16 tensor-core GEMM (m16n8k16), 2-stage pipeline ---------
// C[M,ldc] = A[M,lda] @ B^T + bias (+fp16 resid). A:[m][k] fp16, B:[n][k] fp16.
// Epilogue: v = acc*oscale; EXPSC: store 2^v as fp16 via ex2.approx.f16x2
// (oscale carries /8*log2e); else +bias/+resid, store fp16 (OUTH) or f32.
// COLSUM: per-column sums of stored values accumulated into csout via atomics.
// ZRS: blocks with blockIdx.x==0 zero csout[m0..m0+127] (next-kernel ordering).
template<int BN, bool HASBIAS, bool RES, bool EXPSC, bool OUTH, bool COLSUM, bool ZRS>
__global__ __launch_bounds__(256, 2)
void mm_h(const __half* __restrict__ A, const __half* __restrict__ B,
          const float* __restrict__ bias, const __half* __restrict__ resid,
          __half* __restrict__ Ch, float* __restrict__ Cf,
          float* __restrict__ csout,
          int K, int lda, int ldb, int ldc, float oscale,
          long long sA, long long sB, long long sC)
{
    constexpr int BM = 128, BK = 32, BKP = 40;
    constexpr int WN = BN / 2;       // warp n-extent (2 warp cols)
    constexpr int NF = WN / 8;       // n-fragments per warp
    __shared__ __align__(16) __half As[2][BM][BKP];
    __shared__ __align__(16) __half Bs[2][BN][BKP];

    const int tid  = threadIdx.x;
    const int lane = tid & 31, warp = tid >> 5;
    const int wr = warp & 3, wc = warp >> 2;
    const int g = lane >> 2, q = lane & 3;
    const int m0 = blockIdx.y * BM;
    const int n0 = blockIdx.x * BN;
    const int z  = blockIdx.z;
    const __half* Ab = A + (size_t)z * sA;
    const __half* Bb = B + (size_t)z * sB;

    if (ZRS && blockIdx.x == 0 && tid < BM)
        csout[(size_t)(m0 + tid)] = 0.f;

    auto stage = [&](int t, int s) {
        const int k0 = t * BK;
        #pragma unroll
        for (int p = 0; p < 2; p++) {                 // A: 128x32 halves = 512 x 16B
            int c = tid + p * 256;
            int r = c >> 2, kc = (c & 3) << 3;
            uint32_t sa = (uint32_t)__cvta_generic_to_shared(&As[s][r][kc]);
            cpasync16(sa, Ab + (size_t)(m0 + r) * lda + k0 + kc);
        }
        #pragma unroll
        for (int p = 0; p < BN / 64; p++) {           // B: BNx32 halves
            int c = tid + p * 256;
            int r = c >> 2, kc = (c & 3) << 3;
            uint32_t sa = (uint32_t)__cvta_generic_to_shared(&Bs[s][r][kc]);
            cpasync16(sa, Bb + (size_t)(n0 + r) * ldb + k0 + kc);
        }
        asm volatile("cp.async.commit_group;");
    };

    float acc[2][NF][4];
    #pragma unroll
    for (int i = 0; i < 2; i++)
        #pragma unroll
        for (int j = 0; j < NF; j++)
            #pragma unroll
            for (int c = 0; c < 4; c++) acc[i][j][c] = 0.f;

    const int mw = wr * 32;
    const int nw = wc * WN;
    const int T = K / BK;

    stage(0, 0);
    for (int t = 0; t < T; t++) {
        if (t + 1 < T) { stage(t + 1, (t + 1) & 1); asm volatile("cp.async.wait_group 1;"); }
        else           { asm volatile("cp.async.wait_group 0;"); }
        __syncthreads();
        const int s = t & 1;
        #pragma unroll
        for (int ks = 0; ks < BK; ks += 16) {
            uint32_t af[2][4];
            #pragma unroll
            for (int i = 0; i < 2; i++) {
                af[i][0] = *(const uint32_t*)&As[s][mw + i*16 + g    ][ks + 2*q    ];
                af[i][1] = *(const uint32_t*)&As[s][mw + i*16 + g + 8][ks + 2*q    ];
                af[i][2] = *(const uint32_t*)&As[s][mw + i*16 + g    ][ks + 2*q + 8];
                af[i][3] = *(const uint32_t*)&As[s][mw + i*16 + g + 8][ks + 2*q + 8];
            }
            uint32_t bf[NF][2];
            #pragma unroll
            for (int j = 0; j < NF; j++) {
                int n = nw + j * 8 + g;
                bf[j][0] = *(const uint32_t*)&Bs[s][n][ks + 2*q    ];
                bf[j][1] = *(const uint32_t*)&Bs[s][n][ks + 2*q + 8];
            }
            #pragma unroll
            for (int i = 0; i < 2; i++)
                #pragma unroll
                for (int j = 0; j < NF; j++)
                    asm volatile(
                        "mma.sync.aligned.m16n8k16.row.col.f32.f16.f16.f32 "
                        "{%0,%1,%2,%3}, {%4,%5,%6,%7}, {%8,%9}, {%0,%1,%2,%3};"
                        : "+f"(acc[i][j][0]), "+f"(acc[i][j][1]),
                          "+f"(acc[i][j][2]), "+f"(acc[i][j][3])
                        : "r"(af[i][0]), "r"(af[i][1]), "r"(af[i][2]), "r"(af[i][3]),
                          "r"(bf[j][0]), "r"(bf[j][1]));
        }
        __syncthreads();
    }

    float cs[COLSUM ? NF : 1][2];
    if (COLSUM)
        #pragma unroll
        for (int j = 0; j < NF; j++) { cs[j][0] = 0.f; cs[j][1] = 0.f; }

    #pragma unroll
    for (int i = 0; i < 2; i++) {
        #pragma unroll
        for (int j = 0; j < NF; j++) {
            int col = n0 + nw + j * 8 + 2 * q;
            #pragma unroll
            for (int hh = 0; hh < 2; hh++) {
                size_t row = (size_t)(m0 + mw + i * 16 + g + hh * 8);
                float v0 = acc[i][j][hh * 2 + 0] * oscale;
                float v1 = acc[i][j][hh * 2 + 1] * oscale;
                if (EXPSC) {
                    // E = 2^(s*log2e/8): one MUFU op per two elements
                    __half2 ah = __floats2half2_rn(v0, v1);
                    uint32_t eu;
                    asm("ex2.approx.f16x2 %0, %1;" : "=r"(eu) : "r"(*(uint32_t*)&ah));
                    *(uint32_t*)&(Ch + (size_t)z * sC)[row * ldc + col] = eu;
                    if (COLSUM) {
                        float2 ef = __half22float2(*(__half2*)&eu);
                        cs[j][0] += ef.x; cs[j][1] += ef.y;
                    }
                } else {
                    if (HASBIAS){ v0 += bias[col]; v1 += bias[col + 1]; }
                    if (RES) {
                        __half2 rv = *(const __half2*)&resid[row * ldc + col];
                        float2 rf = __half22float2(rv);
                        v0 += rf.x; v1 += rf.y;
                    }
                    if (OUTH) {
                        __half2 hv = __floats2half2_rn(v0, v1);
                        *(uint32_t*)&(Ch + (size_t)z * sC)[row * ldc + col] =
                            *(uint32_t*)&hv;
                    } else {
                        *(float2*)&(Cf + (size_t)z * sC)[row * ldc + col] =
                            make_float2(v0, v1);
                    }
                }
            }
        }
    }

    if (COLSUM) {
        #pragma unroll
        for (int j = 0; j < NF; j++) {
            #pragma unroll
            for (int c = 0; c < 2; c++) {
                float v = cs[j][c];
                v += __shfl_xor_sync(0xffffffffu, v, 4);
                v += __shfl_xor_sync(0xffffffffu, v, 8);
                v += __shfl_xor_sync(0xffffffffu, v, 16);
                if (g == 0)
                    atomicAdd(&csout[(size_t)z * SEQ + n0 + nw + j * 8 + 2 * q + c], v);
            }
        }
    }
}

// ---------------- vt[b][d][key] = v[b,key,d] * 1024/sum (smem transpose) -----
__global__ __launch_bounds__(256)
void scalevt_k(const __half* __restrict__ qkv, const float* __restrict__ rs,
               __half* __restrict__ vt)
{
    __shared__ __align__(16) __half sm[64][72];   // 144B row stride: uint4-safe
    __shared__ float rsm[64];
    const int b = blockIdx.y;
    const int key0 = blockIdx.x * 64;
    const int tid = threadIdx.x;
    #pragma unroll
    for (int p = 0; p < 2; p++) {
        int c = tid + p * 256;                 // 512 chunks of 8 halves
        int kr = c >> 3, d8 = (c & 7) << 3;
        *(uint4*)&sm[kr][d8] =
            *(const uint4*)&qkv[((size_t)(b * SEQ + key0 + kr)) * 192 + 128 + d8];
    }
    if (tid < 64) rsm[tid] = 1024.f / rs[b * SEQ + key0 + tid];
    __syncthreads();
    #pragma unroll
    for (int p = 0; p < 2; p++) {
        int c = tid + p * 256;
        int d = c >> 3, k8 = (c & 7) << 3;
        uint4 o;
        uint32_t* ow = (uint32_t*)&o;
        #pragma unroll
        for (int i = 0; i < 4; i++) {
            float f0 = __half2float(sm[k8 + 2*i    ][d]) * rsm[k8 + 2*i    ];
            float f1 = __half2float(sm[k8 + 2*i + 1][d]) * rsm[k8 + 2*i + 1];
            __half2 hv = __floats2half2_rn(f0, f1);
            ow[i] = *(uint32_t*)&hv;
        }
        *(uint4*)&vt[((size_t)(b * HD + d)) * SEQ + key0 + k8] = o;
    }
}

// ---------------- LayerNorm: warp-per-row, 8 rows/block ----------------------
template<bool F32OUT>
__global__ __launch_bounds__(256)
void ln_kernel(const float* __restrict__ in, const float* __restrict__ gamma,
               const float* __restrict__ beta, float* __restrict__ outf,
               __half* __restrict__ outh)
{
    const int warp = threadIdx.x >> 5, lane = threadIdx.x & 31;
    const size_t row = (size_t)blockIdx.x * 8 + warp;
    const float4* ip = (const float4*)(in + row * DM);

    float4 v[4];
    float s = 0.f, ss = 0.f;
    #pragma unroll
    for (int i = 0; i < 4; i++) {
        v[i] = ip[lane + 32 * i];
        s  += v[i].x + v[i].y + v[i].z + v[i].w;
        ss += v[i].x*v[i].x + v[i].y*v[i].y + v[i].z*v[i].z + v[i].w*v[i].w;
    }
    #pragma unroll
    for (int o = 16; o > 0; o >>= 1) {
        s  += __shfl_xor_sync(0xffffffffu, s,  o);
        ss += __shfl_xor_sync(0xffffffffu, ss, o);
    }
    const float mu  = s * (1.f / DM);
    const float var = ss * (1.f / DM) - mu * mu;
    const float inv = rsqrtf(var + 1e-5f);

    #pragma unroll
    for (int i = 0; i < 4; i++) {
        float4 g = ((const float4*)gamma)[lane + 32 * i];
        float4 b = ((const float4*)beta)[lane + 32 * i];
        float4 o;
        o.x = (v[i].x - mu) * inv * g.x + b.x;
        o.y = (v[i].y - mu) * inv * g.y + b.y;
        o.z = (v[i].z - mu) * inv * g.z + b.z;
        o.w = (v[i].w - mu) * inv * g.w + b.w;
        if (F32OUT) {
            ((float4*)(outf + row * DM))[lane + 32 * i] = o;
        } else {
            __half2 h0 = __floats2half2_rn(o.x, o.y);
            __half2 h1 = __floats2half2_rn(o.z, o.w);
            *(uint2*)&outh[row * DM + (lane + 32 * i) * 4] =
                make_uint2(*(uint32_t*)&h0, *(uint32_t*)&h1);
        }
    }
}

// ---------------- prep kernels ----------------------------------------------
__global__ void prep_wqkv(const float* wq, const float* wk, const float* wv,
                          const float* bq, const float* bk, const float* bv,
                          __half* wT, float* bias)
{
    int idx = blockIdx.x * 256 + threadIdx.x;
    if (idx < DM * 192) {
        int c = idx / DM, r = idx % DM;
        float v = (c < 64) ? wq[r*64 + c] : (c < 128 ? wk[r*64 + c - 64] : wv[r*64 + c - 128]);
        wT[idx] = __float2half_rn(v);
    }
    if (idx < 192)
        bias[idx] = (idx < 64) ? bq[idx] : (idx < 128 ? bk[idx - 64] : bv[idx - 128]);
}

__global__ void prep_weff(const float* __restrict__ wo, __half* __restrict__ wT)
{
    int idx = blockIdx.x * 256 + threadIdx.x;
    if (idx < DM * HD) {
        int c = idx / HD, r = idx % HD;
        float s = 0.f;
        #pragma unroll
        for (int h = 0; h < 8; h++) s += wo[(size_t)(h*HD + r) * DM + c];
        wT[idx] = __float2half_rn(s);
    }
}

// Tiled transpose W[R][C] -> T[C][R] fp16 (coalesced loads AND stores)
__global__ __launch_bounds__(256)
void prep_t(const float* __restrict__ W, __half* __restrict__ T, int R, int C)
{
    __shared__ __half sm[32][33];
    const int c0 = blockIdx.x * 32;
    const int r0 = blockIdx.y * 32;
    const int lx = threadIdx.x & 31, ly = threadIdx.x >> 5;   // 32 x 8
    #pragma unroll
    for (int i = 0; i < 4; i++) {
        int r = r0 + ly + i * 8;
        sm[ly + i * 8][lx] = __float2half_rn(W[(size_t)r * C + c0 + lx]);
    }
    __syncthreads();
    #pragma unroll
    for (int i = 0; i < 4; i++) {
        int c = c0 + ly + i * 8;
        T[(size_t)c * R + r0 + lx] = sm[lx][ly + i * 8];
    }
}

__global__ void cvt_h(const float* __restrict__ in, __half* __restrict__ out)
{
    int idx = blockIdx.x * 256 + threadIdx.x;   // one float4 -> half4 each
    float4 v = ((const float4*)in)[idx];
    __half2 h0 = __floats2half2_rn(v.x, v.y);
    __half2 h1 = __floats2half2_rn(v.z, v.w);
    ((uint2*)out)[idx] = make_uint2(*(uint32_t*)&h0, *(uint32_t*)&h1);
}

// bff[n] = b2[n] + sum_k b1[k] * w2[k][n]  — parallel over k-slices
__global__ __launch_bounds__(256)
void prep_bff(const float* __restrict__ b1, const float* __restrict__ w2,
              const float* __restrict__ b2, float* __restrict__ bff)
{
    __shared__ float sm[8][32];
    const int nloc = threadIdx.x & 31;
    const int slice = threadIdx.x >> 5;          // 8 slices x 256 k
    const int n = blockIdx.x * 32 + nloc;
    float s = 0.f;
    const int k0 = slice * 256;
    #pragma unroll 8
    for (int k = k0; k < k0 + 256; k++)
        s += b1[k] * w2[(size_t)k * DM + n];
    sm[slice][nloc] = s;
    __syncthreads();
    if (slice == 0) {
        float t = b2[n];
        #pragma unroll
        for (int r = 0; r < 8; r++) t += sm[r][nloc];
        bff[n] = t;
    }
}

// ---------------- host orchestration ----------------------------------------
extern "C" void kernel_launch(void* const* d_in, const int* in_sizes, int n_in,
                              void* d_out, int out_size)
{
    (void)in_sizes; (void)n_in; (void)out_size;
    const float* x   = (const float*)d_in[0];
    const float* wq  = (const float*)d_in[1];
    const float* bq  = (const float*)d_in[2];
    const float* wk  = (const float*)d_in[3];
    const float* bk  = (const float*)d_in[4];
    const float* wv  = (const float*)d_in[5];
    const float* bv  = (const float*)d_in[6];
    const float* wo  = (const float*)d_in[7];
    const float* bo  = (const float*)d_in[8];
    const float* lng = (const float*)d_in[9];
    const float* lnb = (const float*)d_in[10];
    const float* w1  = (const float*)d_in[11];
    const float* b1  = (const float*)d_in[12];
    const float* w2  = (const float*)d_in[13];
    const float* b2  = (const float*)d_in[14];
    float* out = (float*)d_out;

    __half *xh, *qkvh, *Eh, *vt, *headh, *hh, *wqkvT, *weffT, *w1h, *w2t, *W12T;
    float *rs, *t1, *t2, *bqkvD, *bffD;
    cudaGetSymbolAddress((void**)&xh,    g_xh);
    cudaGetSymbolAddress((void**)&qkvh,  g_qkvh);
    cudaGetSymbolAddress((void**)&Eh,    g_Eh);
    cudaGetSymbolAddress((void**)&rs,    g_rs);
    cudaGetSymbolAddress((void**)&vt,    g_vt);
    cudaGetSymbolAddress((void**)&headh, g_headh);
    cudaGetSymbolAddress((void**)&t1,    g_t1);
    cudaGetSymbolAddress((void**)&hh,    g_hh);
    cudaGetSymbolAddress((void**)&t2,    g_t2);
    cudaGetSymbolAddress((void**)&wqkvT, g_wqkvT);
    cudaGetSymbolAddress((void**)&bqkvD, g_bqkv);
    cudaGetSymbolAddress((void**)&weffT, g_weffT);
    cudaGetSymbolAddress((void**)&w1h,   g_w1h);
    cudaGetSymbolAddress((void**)&w2t,   g_w2t);
    cudaGetSymbolAddress((void**)&W12T,  g_W12T);
    cudaGetSymbolAddress((void**)&bffD,  g_bff);

    // prep: transpose/convert weights, fold FF weights, fp16 input copy
    prep_wqkv<<<(DM*192 + 255)/256, 256>>>(wq, wk, wv, bq, bk, bv, wqkvT, bqkvD);
    prep_weff<<<(DM*HD + 255)/256, 256>>>(wo, weffT);
    cvt_h<<<(DM*DFF/4)/256, 256>>>(w1, w1h);
    prep_t<<<dim3(DM/32, DFF/32), 256>>>(w2, w2t, DFF, DM);
    prep_bff<<<DM/32, 256>>>(b1, w2, b2, bffD);
    cvt_h<<<((size_t)MTOT*DM/4)/256, 256>>>(x, xh);

    // W12T[n][m] = sum_k w2t[n][k] * w1h[m][k]  (=(w1@w2)^T, fp16)
    mm_h<64, false, false, false, true, false, false><<<dim3(DM/64, DM/128), 256>>>(
        w2t, w1h, nullptr, nullptr, W12T, nullptr, nullptr,
        DFF, DFF, DFF, DM, 1.f, 0, 0, 0);

    const float EXPSCALE = 0.125f * 1.4426950408889634f;  // /8 * log2(e)

    for (int L = 0; L < NLAYERS; L++) {
        // fused QKV: [16384,192] = x @ Wqkv + bqkv -> fp16 ; also zeros rs
        mm_h<64, true, false, false, true, false, true><<<dim3(3, 128, 1), 256>>>(
            xh, wqkvT, bqkvD, nullptr, qkvh, nullptr, rs,
            DM, DM, DM, 192, 1.f, 0, 0, 0);

        // E = 2^(q@k^T * log2e/8) per batch -> fp16, with fused column sums
        mm_h<128, false, false, true, true, true, false><<<dim3(8, 8, 16), 256>>>(
            qkvh, qkvh + 64, nullptr, nullptr, Eh, nullptr, rs,
            HD, 192, 192, SEQ, EXPSCALE,
            (long long)SEQ * 192, (long long)SEQ * 192, (long long)SEQ * SEQ);

        // vt = (v * 1024/sum)^T
        scalevt_k<<<dim3(SEQ/64, BATCH), 256>>>(qkvh, rs, vt);

        // head = (E @ vt^T) / 1024 per batch -> fp16
        mm_h<64, false, false, false, true, false, false><<<dim3(1, 8, 16), 256>>>(
            Eh, vt, nullptr, nullptr, headh, nullptr, nullptr,
            SEQ, SEQ, SEQ, HD, 1.f / 1024.f,
            (long long)SEQ * SEQ, (long long)HD * SEQ, (long long)SEQ * HD);

        // t1 = head @ weff + bo + x(fp16) ; h = LN(t1) -> fp16
        mm_h<128, true, true, false, false, false, false><<<dim3(4, 128, 1), 256>>>(
            headh, weffT, bo, xh, nullptr, t1, nullptr,
            HD, HD, HD, DM, 1.f, 0, 0, 0);
        ln_kernel<false><<<MTOT/8, 256>>>(t1, lng, lnb, nullptr, hh);

        // folded FF: t2 = h @ W12 + bff + h(fp16)
        mm_h<128, true, true, false, false, false, false><<<dim3(4, 128, 1), 256>>>(
            hh, W12T, bffD, hh, nullptr, t2, nullptr,
            DM, DM, DM, DM, 1.f, 0, 0, 0);

        if (L == NLAYERS - 1)
            ln_kernel<true><<<MTOT/8, 256>>>(t2, lng, lnb, out, nullptr);
        else
            ln_kernel<false><<<MTOT/8, 256>>>(t2, lng, lnb, nullptr, xh);
    }
}